// round 9
// baseline (speedup 1.0000x reference)
#include <cuda_runtime.h>

#define DI __device__ __forceinline__

namespace {
constexpr int Bsz = 2;
constexpr int Nq  = 4096;
constexpr int Nkv = 4096;
constexpr int ENC = 768;
constexpr int DEC = 512;
constexpr int NH  = 8;
constexpr int HD  = 64;
constexpr float SCALE_L2E = 0.125f * 1.4426950408889634f;  // SCALE * log2(e)
}

// Scratch (allocation-free: static device globals)
__device__ float g_q[(size_t)Bsz * NH * Nq  * HD];  // [B,H,N,64]
__device__ float g_k[(size_t)Bsz * NH * Nkv * HD];  // [B,H,Ny,64]
__device__ float g_v[(size_t)Bsz * NH * Nkv * HD];  // [B,H,Ny,64]
__device__ float g_o[(size_t)Bsz * Nq * DEC];       // [B,N,512]

DI unsigned f2tf(float x) {
    unsigned r;
    asm("cvt.rna.tf32.f32 %0, %1;" : "=r"(r) : "f"(x));
    return r;
}

DI uint4 f2tf4(float4 v) {
    return uint4{f2tf(v.x), f2tf(v.y), f2tf(v.z), f2tf(v.w)};
}

DI unsigned packbf(float hi, float lo) {   // word = {lo, hi} bf16x2
    unsigned r;
    asm("cvt.rn.bf16x2.f32 %0, %1, %2;" : "=r"(r) : "f"(hi), "f"(lo));
    return r;
}

DI float ex2(float x) {
    float r;
    asm("ex2.approx.ftz.f32 %0, %1;" : "=f"(r) : "f"(x));
    return r;
}

DI void mma_tf32(float c[4], unsigned a0, unsigned a1, unsigned a2, unsigned a3,
                 unsigned b0, unsigned b1) {
    asm volatile(
        "mma.sync.aligned.m16n8k8.row.col.f32.tf32.tf32.f32 "
        "{%0,%1,%2,%3}, {%4,%5,%6,%7}, {%8,%9}, {%0,%1,%2,%3};"
        : "+f"(c[0]), "+f"(c[1]), "+f"(c[2]), "+f"(c[3])
        : "r"(a0), "r"(a1), "r"(a2), "r"(a3), "r"(b0), "r"(b1));
}

DI void mma_bf16(float c[4], unsigned a0, unsigned a1, unsigned a2, unsigned a3,
                 unsigned b0, unsigned b1) {
    asm volatile(
        "mma.sync.aligned.m16n8k16.row.col.f32.bf16.bf16.f32 "
        "{%0,%1,%2,%3}, {%4,%5,%6,%7}, {%8,%9}, {%0,%1,%2,%3};"
        : "+f"(c[0]), "+f"(c[1]), "+f"(c[2]), "+f"(c[3])
        : "r"(a0), "r"(a1), "r"(a2), "r"(a3), "r"(b0), "r"(b1));
}

// ---------------------------------------------------------------------------
// GEMM-NT on tensor pipe (tf32 m16n8k8) + register-prefetch pipelining.
// Block 256 thr = 8 warps. BM=128, BN=64, BK=32.
// ---------------------------------------------------------------------------
template<int MODE, int K>
__global__ __launch_bounds__(256, 2) void gemm_mma(const float* __restrict__ A,
                                                   const float* __restrict__ Bw,
                                                   float* __restrict__ Cout,
                                                   const float* __restrict__ bias)
{
    __shared__ __align__(16) unsigned As[128 * 36];
    __shared__ __align__(16) unsigned Bs[64 * 36];

    const int tid  = threadIdx.x;
    const int w    = tid >> 5;
    const int lane = tid & 31;
    const int g    = lane >> 2;
    const int c    = lane & 3;
    const int m0   = blockIdx.y << 7;
    const int n0   = blockIdx.x << 6;

    const int arow = tid >> 3;            // 0..31
    const int acol = (tid & 7) << 2;      // 0,4,..,28

    const float* Abase = (MODE == 2) ? g_o : A;
    const float* aptr = Abase + (size_t)(m0 + arow) * K + acol;
    const float* bptr = Bw    + (size_t)(n0 + arow) * K + acol;

    float acc[8][4] = {};
    float4 fa[4], fb[2];

    // prologue: prefetch chunk 0
    #pragma unroll
    for (int u = 0; u < 4; ++u) fa[u] = *(const float4*)(aptr + (size_t)(32 * u) * K);
    #pragma unroll
    for (int u = 0; u < 2; ++u) fb[u] = *(const float4*)(bptr + (size_t)(32 * u) * K);

    for (int k0 = 0; k0 < K; k0 += 32) {
        __syncthreads();   // all warps done reading previous chunk
        #pragma unroll
        for (int u = 0; u < 4; ++u)
            *(uint4*)(As + (arow + 32 * u) * 36 + acol) = f2tf4(fa[u]);
        #pragma unroll
        for (int u = 0; u < 2; ++u)
            *(uint4*)(Bs + (arow + 32 * u) * 36 + acol) = f2tf4(fb[u]);
        __syncthreads();

        if (k0 + 32 < K) {   // issue next-chunk loads; they overlap the MMAs
            #pragma unroll
            for (int u = 0; u < 4; ++u)
                fa[u] = *(const float4*)(aptr + (size_t)(32 * u) * K + k0 + 32);
            #pragma unroll
            for (int u = 0; u < 2; ++u)
                fb[u] = *(const float4*)(bptr + (size_t)(32 * u) * K + k0 + 32);
        }

        #pragma unroll
        for (int kk = 0; kk < 4; ++kk) {
            const unsigned a0 = As[(w * 16 + g    ) * 36 + kk * 8 + c];
            const unsigned a1 = As[(w * 16 + g + 8) * 36 + kk * 8 + c];
            const unsigned a2 = As[(w * 16 + g    ) * 36 + kk * 8 + c + 4];
            const unsigned a3 = As[(w * 16 + g + 8) * 36 + kk * 8 + c + 4];
            #pragma unroll
            for (int j = 0; j < 8; ++j) {
                const unsigned b0 = Bs[(j * 8 + g) * 36 + kk * 8 + c];
                const unsigned b1 = Bs[(j * 8 + g) * 36 + kk * 8 + c + 4];
                mma_tf32(acc[j], a0, a1, a2, a3, b0, b1);
            }
        }
    }

    #pragma unroll
    for (int j = 0; j < 8; ++j) {
        const int n = n0 + j * 8 + 2 * c;
        #pragma unroll
        for (int half = 0; half < 2; ++half) {
            const int m = m0 + w * 16 + g + half * 8;
            float2 val = {acc[j][2 * half], acc[j][2 * half + 1]};
            if (MODE == 0) {
                const int b = m >> 12, nn = m & 4095, h = n >> 6, d = n & 63;
                *(float2*)&g_q[(((size_t)(b * NH + h)) * Nq + nn) * HD + d] = val;
            } else if (MODE == 1) {
                const int b = m >> 12, nn = m & 4095;
                if (n < DEC) {
                    const int h = n >> 6, d = n & 63;
                    *(float2*)&g_k[(((size_t)(b * NH + h)) * Nkv + nn) * HD + d] = val;
                } else {
                    const int n2 = n - DEC, h = n2 >> 6, d = n2 & 63;
                    *(float2*)&g_v[(((size_t)(b * NH + h)) * Nkv + nn) * HD + d] = val;
                }
            } else {
                float2 bb = *(const float2*)&bias[n];
                val.x += bb.x; val.y += bb.y;
                *(float2*)&Cout[(size_t)m * DEC + n] = val;
            }
        }
    }
}

// ---------------------------------------------------------------------------
// Flash attention, bf16 mma.m16n8k16 + register-prefetch pipelining.
// Layouts identical to R8 (passing): Kw key-major pairs pad36; Vt dim-major,
// XOR-swizzled; P C-frag == A-frag (no shuffles).
// ---------------------------------------------------------------------------
__global__ __launch_bounds__(256, 2) void attn_kernel(const int* __restrict__ kpm)
{
    __shared__ __align__(16) unsigned Kw[64 * 36];
    __shared__ __align__(16) unsigned Vt[64 * 36];
    __shared__ float Msk[64];

    const int tid  = threadIdx.x;
    const int w    = tid >> 5;
    const int lane = tid & 31;
    const int g    = lane >> 2;
    const int c    = lane & 3;
    const int bh   = blockIdx.y;
    const int b    = bh >> 3;
    const int h    = bh & 7;
    const int n0   = blockIdx.x << 7;

    const float* qb = g_q + ((size_t)bh * Nq + n0) * HD;
    const float* kb = g_k + (size_t)bh * Nkv * HD;
    const float* vb = g_v + (size_t)bh * Nkv * HD;
    const int*   mb = kpm + b * Nkv;

    // per-thread staging coordinates
    const int krow = tid >> 2;            // 0..63 (key)
    const int kcol = (tid & 3) << 2;      // dim base 0,4,8,12 -> two u-iters cover 0..15? no:
    // K staging uses chunk = tid + 256u: row = chunk>>4, c4 = (chunk&15)<<2
    const int d4v = tid & 15;             // V staging dim quad
    const int rpv = tid >> 4;             // V staging key pair (0..15) + 16u

    (void)krow; (void)kcol;

    // ---- prefetch tile 0 (issued before Q staging; overlaps it) ----
    float4 fk[4], fva[2], fvb[2];
    int mreg = 0;
    #pragma unroll
    for (int u = 0; u < 4; ++u) {
        const int chunk = tid + 256 * u;
        fk[u] = *(const float4*)(kb + (size_t)(chunk >> 4) * HD + ((chunk & 15) << 2));
    }
    #pragma unroll
    for (int u = 0; u < 2; ++u) {
        const int rp = rpv + 16 * u;
        const float* v0 = vb + (size_t)(2 * rp) * HD + d4v * 4;
        fva[u] = *(const float4*)v0;
        fvb[u] = *(const float4*)(v0 + HD);
    }
    if (tid < 64) mreg = mb[tid];

    // ---- Stage Q (128x64) as bf16 words through Kw/Vt, pull A-frags ----
    #pragma unroll
    for (int u = 0; u < 8; ++u) {
        const int chunk = tid + 256 * u;
        const int row = chunk >> 4;
        const int c4  = (chunk & 15) << 2;
        float4 qv = *(const float4*)(qb + (size_t)row * HD + c4);
        uint2 qt = {packbf(qv.y, qv.x), packbf(qv.w, qv.z)};
        unsigned* base = (row < 64) ? Kw : Vt;
        *(uint2*)(base + (row & 63) * 36 + (c4 >> 1)) = qt;
    }
    __syncthreads();

    unsigned qa[4][4];
    {
        const unsigned* Qb = (w < 4) ? Kw : Vt;
        const int rb = (w * 16) & 63;
        #pragma unroll
        for (int kk = 0; kk < 4; ++kk) {
            qa[kk][0] = Qb[(rb + g    ) * 36 + kk * 8 + c];
            qa[kk][1] = Qb[(rb + g + 8) * 36 + kk * 8 + c];
            qa[kk][2] = Qb[(rb + g    ) * 36 + kk * 8 + c + 4];
            qa[kk][3] = Qb[(rb + g + 8) * 36 + kk * 8 + c + 4];
        }
    }

    float o[8][4] = {};
    float mr0 = -1e30f, mr1 = -1e30f, l0 = 0.f, l1 = 0.f;

    for (int t = 0; t < Nkv; t += 64) {
        __syncthreads();   // prior-iter smem reads (and qa pulls) complete

        // ---- STS staged tile t (convert/pack now; data arrived long ago) ----
        #pragma unroll
        for (int u = 0; u < 4; ++u) {
            const int chunk = tid + 256 * u;
            uint2 kt = {packbf(fk[u].y, fk[u].x), packbf(fk[u].w, fk[u].z)};
            *(uint2*)(Kw + (chunk >> 4) * 36 + (((chunk & 15) << 2) >> 1)) = kt;
        }
        #pragma unroll
        for (int u = 0; u < 2; ++u) {
            const int rp = rpv + 16 * u;
            const int d0 = d4v * 4;
            Vt[(d0 + 0) * 36 + (rp ^ (((d0 + 0) >> 3) & 7))] = packbf(fvb[u].x, fva[u].x);
            Vt[(d0 + 1) * 36 + (rp ^ (((d0 + 1) >> 3) & 7))] = packbf(fvb[u].y, fva[u].y);
            Vt[(d0 + 2) * 36 + (rp ^ (((d0 + 2) >> 3) & 7))] = packbf(fvb[u].z, fva[u].z);
            Vt[(d0 + 3) * 36 + (rp ^ (((d0 + 3) >> 3) & 7))] = packbf(fvb[u].w, fva[u].w);
        }
        if (tid < 64) Msk[tid] = mreg ? -1e30f : 0.f;
        __syncthreads();

        // ---- issue prefetch for tile t+64 (overlaps all compute below) ----
        if (t + 64 < Nkv) {
            #pragma unroll
            for (int u = 0; u < 4; ++u) {
                const int chunk = tid + 256 * u;
                fk[u] = *(const float4*)(kb + (size_t)(t + 64 + (chunk >> 4)) * HD
                                            + ((chunk & 15) << 2));
            }
            #pragma unroll
            for (int u = 0; u < 2; ++u) {
                const int rp = rpv + 16 * u;
                const float* v0 = vb + (size_t)(t + 64 + 2 * rp) * HD + d4v * 4;
                fva[u] = *(const float4*)v0;
                fvb[u] = *(const float4*)(v0 + HD);
            }
            if (tid < 64) mreg = mb[t + 64 + tid];
        }

        // ---- S = Q @ K^T (bf16 k16) ----
        float s[8][4] = {};
        #pragma unroll
        for (int kk = 0; kk < 4; ++kk) {
            #pragma unroll
            for (int j = 0; j < 8; ++j) {
                const unsigned b0 = Kw[(j * 8 + g) * 36 + kk * 8 + c];
                const unsigned b1 = Kw[(j * 8 + g) * 36 + kk * 8 + c + 4];
                mma_bf16(s[j], qa[kk][0], qa[kk][1], qa[kk][2], qa[kk][3], b0, b1);
            }
        }

        // ---- scale(log2 domain) + mask + online softmax ----
        float vm0 = -1e30f, vm1 = -1e30f;
        #pragma unroll
        for (int j = 0; j < 8; ++j) {
            const float mk0 = Msk[j * 8 + 2 * c];
            const float mk1 = Msk[j * 8 + 2 * c + 1];
            s[j][0] = fmaf(s[j][0], SCALE_L2E, mk0);
            s[j][1] = fmaf(s[j][1], SCALE_L2E, mk1);
            s[j][2] = fmaf(s[j][2], SCALE_L2E, mk0);
            s[j][3] = fmaf(s[j][3], SCALE_L2E, mk1);
            vm0 = fmaxf(vm0, fmaxf(s[j][0], s[j][1]));
            vm1 = fmaxf(vm1, fmaxf(s[j][2], s[j][3]));
        }
        vm0 = fmaxf(vm0, __shfl_xor_sync(0xffffffffu, vm0, 1));
        vm0 = fmaxf(vm0, __shfl_xor_sync(0xffffffffu, vm0, 2));
        vm1 = fmaxf(vm1, __shfl_xor_sync(0xffffffffu, vm1, 1));
        vm1 = fmaxf(vm1, __shfl_xor_sync(0xffffffffu, vm1, 2));

        const float mn0 = fmaxf(mr0, vm0);
        const float mn1 = fmaxf(mr1, vm1);
        const float cr0 = ex2(mr0 - mn0);
        const float cr1 = ex2(mr1 - mn1);
        mr0 = mn0; mr1 = mn1;

        float rs0 = 0.f, rs1 = 0.f;
        #pragma unroll
        for (int j = 0; j < 8; ++j) {
            s[j][0] = ex2(s[j][0] - mn0);
            s[j][1] = ex2(s[j][1] - mn0);
            s[j][2] = ex2(s[j][2] - mn1);
            s[j][3] = ex2(s[j][3] - mn1);
            rs0 += s[j][0] + s[j][1];
            rs1 += s[j][2] + s[j][3];
        }
        rs0 += __shfl_xor_sync(0xffffffffu, rs0, 1);
        rs0 += __shfl_xor_sync(0xffffffffu, rs0, 2);
        rs1 += __shfl_xor_sync(0xffffffffu, rs1, 1);
        rs1 += __shfl_xor_sync(0xffffffffu, rs1, 2);
        l0 = l0 * cr0 + rs0;
        l1 = l1 * cr1 + rs1;

        #pragma unroll
        for (int j = 0; j < 8; ++j) {
            o[j][0] *= cr0; o[j][1] *= cr0;
            o[j][2] *= cr1; o[j][3] *= cr1;
        }

        // ---- O += P @ V : P C-frag IS the k16 A-frag layout ----
        #pragma unroll
        for (int kk = 0; kk < 4; ++kk) {
            const unsigned pa0 = packbf(s[2 * kk    ][1], s[2 * kk    ][0]);
            const unsigned pa1 = packbf(s[2 * kk    ][3], s[2 * kk    ][2]);
            const unsigned pa2 = packbf(s[2 * kk + 1][1], s[2 * kk + 1][0]);
            const unsigned pa3 = packbf(s[2 * kk + 1][3], s[2 * kk + 1][2]);
            #pragma unroll
            for (int j = 0; j < 8; ++j) {
                const unsigned b0 = Vt[(j * 8 + g) * 36 + ((kk * 8 + c    ) ^ j)];
                const unsigned b1 = Vt[(j * 8 + g) * 36 + ((kk * 8 + c + 4) ^ j)];
                mma_bf16(o[j], pa0, pa1, pa2, pa3, b0, b1);
            }
        }
    }

    // ---- normalize + write to [B,N,512] ----
    const float inv0 = 1.f / l0;
    const float inv1 = 1.f / l1;
    float* ob = g_o + ((size_t)(b * Nq) + n0 + w * 16) * DEC + h * 64;
    #pragma unroll
    for (int j = 0; j < 8; ++j) {
        float2 v0 = {o[j][0] * inv0, o[j][1] * inv0};
        float2 v1 = {o[j][2] * inv1, o[j][3] * inv1};
        *(float2*)(ob + (size_t)g * DEC + j * 8 + 2 * c)       = v0;
        *(float2*)(ob + (size_t)(g + 8) * DEC + j * 8 + 2 * c) = v1;
    }
}

// ---------------------------------------------------------------------------
extern "C" void kernel_launch(void* const* d_in, const int* in_sizes, int n_in,
                              void* d_out, int out_size)
{
    (void)in_sizes; (void)n_in; (void)out_size;
    const float* x   = (const float*)d_in[0];
    const float* y   = (const float*)d_in[1];
    const int*   kpm = (const int*)d_in[2];     // bool mask promoted to int32
    const float* Wq  = (const float*)d_in[3];
    const float* Wkv = (const float*)d_in[4];
    const float* Wp  = (const float*)d_in[5];
    const float* bp  = (const float*)d_in[6];
    float* out = (float*)d_out;

    gemm_mma<0, DEC><<<dim3(DEC / 64, Bsz * Nq / 128), 256>>>(x, Wq, nullptr, nullptr);
    gemm_mma<1, ENC><<<dim3(2 * DEC / 64, Bsz * Nkv / 128), 256>>>(y, Wkv, nullptr, nullptr);
    attn_kernel<<<dim3(Nq / 128, Bsz * NH), 256>>>(kpm);
    gemm_mma<2, DEC><<<dim3(DEC / 64, Bsz * Nq / 128), 256>>>(nullptr, Wp, out, bp);
}

// round 10
// speedup vs baseline: 1.1479x; 1.1479x over previous
#include <cuda_runtime.h>

#define DI __device__ __forceinline__

namespace {
constexpr int Bsz = 2;
constexpr int Nq  = 4096;
constexpr int Nkv = 4096;
constexpr int ENC = 768;
constexpr int DEC = 512;
constexpr int NH  = 8;
constexpr int HD  = 64;
constexpr float SCALE_L2E = 0.125f * 1.4426950408889634f;  // SCALE * log2(e)
}

// Scratch (allocation-free: static device globals)
__device__ float g_q[(size_t)Bsz * NH * Nq  * HD];  // [B,H,N,64]
__device__ float g_k[(size_t)Bsz * NH * Nkv * HD];  // [B,H,Ny,64]
__device__ float g_v[(size_t)Bsz * NH * Nkv * HD];  // [B,H,Ny,64]
__device__ float g_o[(size_t)Bsz * Nq * DEC];       // [B,N,512]

DI unsigned packh(float hi, float lo) {    // word = {lo, hi} f16x2
    unsigned r;
    asm("cvt.rn.f16x2.f32 %0, %1, %2;" : "=r"(r) : "f"(hi), "f"(lo));
    return r;
}

DI float ex2(float x) {
    float r;
    asm("ex2.approx.ftz.f32 %0, %1;" : "=f"(r) : "f"(x));
    return r;
}

DI unsigned hex2(unsigned x) {             // ex2 on f16x2 pair
    unsigned r;
    asm("ex2.approx.f16x2 %0, %1;" : "=r"(r) : "r"(x));
    return r;
}

DI void mma_f16(float c[4], unsigned a0, unsigned a1, unsigned a2, unsigned a3,
                unsigned b0, unsigned b1) {
    asm volatile(
        "mma.sync.aligned.m16n8k16.row.col.f32.f16.f16.f32 "
        "{%0,%1,%2,%3}, {%4,%5,%6,%7}, {%8,%9}, {%0,%1,%2,%3};"
        : "+f"(c[0]), "+f"(c[1]), "+f"(c[2]), "+f"(c[3])
        : "r"(a0), "r"(a1), "r"(a2), "r"(a3), "r"(b0), "r"(b1));
}

DI void ldsm4(unsigned& r0, unsigned& r1, unsigned& r2, unsigned& r3, unsigned addr) {
    asm volatile("ldmatrix.sync.aligned.m8n8.x4.shared.b16 {%0,%1,%2,%3}, [%4];"
                 : "=r"(r0), "=r"(r1), "=r"(r2), "=r"(r3) : "r"(addr));
}

// ---------------------------------------------------------------------------
// GEMM-NT, f16 m16n8k16, ldmatrix frags, register-prefetch.
// Block 256 thr = 8 warps. BM=128, BN=64, BK=32.
// ---------------------------------------------------------------------------
template<int MODE, int K>
__global__ __launch_bounds__(256, 2) void gemm_mma(const float* __restrict__ A,
                                                   const float* __restrict__ Bw,
                                                   float* __restrict__ Cout,
                                                   const float* __restrict__ bias)
{
    __shared__ __align__(16) unsigned As[128 * 36];   // rows use words 0..15
    __shared__ __align__(16) unsigned Bs[64 * 36];

    const int tid  = threadIdx.x;
    const int w    = tid >> 5;
    const int lane = tid & 31;
    const int g    = lane >> 2;
    const int c    = lane & 3;
    const int m0   = blockIdx.y << 7;
    const int n0   = blockIdx.x << 6;

    const int arow = tid >> 3;            // 0..31
    const int ac4  = (tid & 7) << 2;      // 0,4,..,28
    const int aw   = (tid & 7) << 1;      // word index

    const float* Abase = (MODE == 2) ? g_o : A;
    const float* aptr = Abase + (size_t)(m0 + arow) * K + ac4;
    const float* bptr = Bw    + (size_t)(n0 + arow) * K + ac4;

    const unsigned asB = (unsigned)__cvta_generic_to_shared(As);
    const unsigned bsB = (unsigned)__cvta_generic_to_shared(Bs);
    const int l7 = lane & 7;

    float acc[8][4] = {};
    float4 fa[4], fb[2];

    #pragma unroll
    for (int u = 0; u < 4; ++u) fa[u] = *(const float4*)(aptr + (size_t)(32 * u) * K);
    #pragma unroll
    for (int u = 0; u < 2; ++u) fb[u] = *(const float4*)(bptr + (size_t)(32 * u) * K);

    for (int k0 = 0; k0 < K; k0 += 32) {
        __syncthreads();
        #pragma unroll
        for (int u = 0; u < 4; ++u) {
            uint2 p = {packh(fa[u].y, fa[u].x), packh(fa[u].w, fa[u].z)};
            *(uint2*)(As + (arow + 32 * u) * 36 + aw) = p;
        }
        #pragma unroll
        for (int u = 0; u < 2; ++u) {
            uint2 p = {packh(fb[u].y, fb[u].x), packh(fb[u].w, fb[u].z)};
            *(uint2*)(Bs + (arow + 32 * u) * 36 + aw) = p;
        }
        __syncthreads();

        if (k0 + 32 < K) {
            #pragma unroll
            for (int u = 0; u < 4; ++u)
                fa[u] = *(const float4*)(aptr + (size_t)(32 * u) * K + k0 + 32);
            #pragma unroll
            for (int u = 0; u < 2; ++u)
                fb[u] = *(const float4*)(bptr + (size_t)(32 * u) * K + k0 + 32);
        }

        // A frags: kk=0,1; x4 = (rows 0-7 / 8-15) x (dim 16B-halves)
        unsigned a[2][4];
        #pragma unroll
        for (int kk = 0; kk < 2; ++kk) {
            unsigned ad = asB + (unsigned)((w * 16 + ((lane >> 3) & 1) * 8 + l7) * 144
                                           + (lane >> 4) * 16 + kk * 32);
            ldsm4(a[kk][0], a[kk][1], a[kk][2], a[kk][3], ad);
        }
        #pragma unroll
        for (int j = 0; j < 8; ++j) {
            unsigned bb[4];
            unsigned bd = bsB + (unsigned)((j * 8 + l7) * 144 + (lane >> 3) * 16);
            ldsm4(bb[0], bb[1], bb[2], bb[3], bd);
            mma_f16(acc[j], a[0][0], a[0][1], a[0][2], a[0][3], bb[0], bb[1]);
            mma_f16(acc[j], a[1][0], a[1][1], a[1][2], a[1][3], bb[2], bb[3]);
        }
    }

    #pragma unroll
    for (int j = 0; j < 8; ++j) {
        const int n = n0 + j * 8 + 2 * c;
        #pragma unroll
        for (int half = 0; half < 2; ++half) {
            const int m = m0 + w * 16 + g + half * 8;
            float2 val = {acc[j][2 * half], acc[j][2 * half + 1]};
            if (MODE == 0) {
                const int b = m >> 12, nn = m & 4095, h = n >> 6, d = n & 63;
                *(float2*)&g_q[(((size_t)(b * NH + h)) * Nq + nn) * HD + d] = val;
            } else if (MODE == 1) {
                const int b = m >> 12, nn = m & 4095;
                if (n < DEC) {
                    const int h = n >> 6, d = n & 63;
                    *(float2*)&g_k[(((size_t)(b * NH + h)) * Nkv + nn) * HD + d] = val;
                } else {
                    const int n2 = n - DEC, h = n2 >> 6, d = n2 & 63;
                    *(float2*)&g_v[(((size_t)(b * NH + h)) * Nkv + nn) * HD + d] = val;
                }
            } else {
                float2 bb = *(const float2*)&bias[n];
                val.x += bb.x; val.y += bb.y;
                *(float2*)&Cout[(size_t)m * DEC + n] = val;
            }
        }
    }
}

// ---------------------------------------------------------------------------
// Flash attention, f16 mma.m16n8k16.
// S B-frags via ldmatrix.x4 on Kw (stride 36 words = 144B, conflict-free).
// PV B-frags scalar from Vt (transposed, XOR-swizzled) — R8-proven layout.
// exp via ex2.approx.f16x2 -> results ARE the PV A-frag words.
// Row sums l via tensor core: P @ ones (b = 0x3C003C00 immediates).
// ---------------------------------------------------------------------------
__global__ __launch_bounds__(256, 2) void attn_kernel(const int* __restrict__ kpm)
{
    __shared__ __align__(16) unsigned Kw[64 * 36];
    __shared__ __align__(16) unsigned Vt[64 * 36];
    __shared__ float Msk[64];

    const int tid  = threadIdx.x;
    const int w    = tid >> 5;
    const int lane = tid & 31;
    const int g    = lane >> 2;
    const int c    = lane & 3;
    const int l7   = lane & 7;
    const int bh   = blockIdx.y;
    const int b    = bh >> 3;
    const int h    = bh & 7;
    const int n0   = blockIdx.x << 7;

    const float* qb = g_q + ((size_t)bh * Nq + n0) * HD;
    const float* kb = g_k + (size_t)bh * Nkv * HD;
    const float* vb = g_v + (size_t)bh * Nkv * HD;
    const int*   mb = kpm + b * Nkv;

    const unsigned kwB = (unsigned)__cvta_generic_to_shared(Kw);
    const unsigned HONE = 0x3C003C00u;   // f16x2 {1.0, 1.0}

    // ---- Stage Q (128x64) as f16 pairs through Kw/Vt, pull A-frags ----
    #pragma unroll
    for (int u = 0; u < 8; ++u) {
        const int chunk = tid + 256 * u;
        const int row = chunk >> 4;
        const int c4  = (chunk & 15) << 2;
        float4 qv = *(const float4*)(qb + (size_t)row * HD + c4);
        uint2 qt = {packh(qv.y, qv.x), packh(qv.w, qv.z)};
        unsigned* base = (row < 64) ? Kw : Vt;
        *(uint2*)(base + (row & 63) * 36 + (c4 >> 1)) = qt;
    }
    __syncthreads();

    unsigned qa[4][4];
    {
        const unsigned* Qb = (w < 4) ? Kw : Vt;
        const int rb = (w * 16) & 63;
        #pragma unroll
        for (int kk = 0; kk < 4; ++kk) {
            qa[kk][0] = Qb[(rb + g    ) * 36 + kk * 8 + c];
            qa[kk][1] = Qb[(rb + g + 8) * 36 + kk * 8 + c];
            qa[kk][2] = Qb[(rb + g    ) * 36 + kk * 8 + c + 4];
            qa[kk][3] = Qb[(rb + g + 8) * 36 + kk * 8 + c + 4];
        }
    }

    float o[8][4] = {};
    float lacc[4] = {};
    float mr0 = -1e30f, mr1 = -1e30f;

    const int d4v = tid & 15;             // V staging dim quad
    const int rpv = tid >> 4;             // V staging key pair base

    for (int t = 0; t < Nkv; t += 64) {
        __syncthreads();   // prior-iter smem reads complete before restaging

        // ---- stage K row-major f16 pairs ----
        #pragma unroll
        for (int u = 0; u < 4; ++u) {
            const int chunk = tid + 256 * u;
            const int row = chunk >> 4;
            const int c4  = (chunk & 15) << 2;
            float4 kv = *(const float4*)(kb + (size_t)(t + row) * HD + c4);
            uint2 kt = {packh(kv.y, kv.x), packh(kv.w, kv.z)};
            *(uint2*)(Kw + row * 36 + (c4 >> 1)) = kt;
        }
        // ---- stage V transposed: word (dim, keypair), swizzled col ----
        #pragma unroll
        for (int u = 0; u < 2; ++u) {
            const int rp = rpv + 16 * u;
            const float* v0 = vb + (size_t)(t + 2 * rp) * HD + d4v * 4;
            float4 a  = *(const float4*)v0;
            float4 bq = *(const float4*)(v0 + HD);
            const int d0 = d4v * 4;
            Vt[(d0 + 0) * 36 + (rp ^ (((d0 + 0) >> 3) & 7))] = packh(bq.x, a.x);
            Vt[(d0 + 1) * 36 + (rp ^ (((d0 + 1) >> 3) & 7))] = packh(bq.y, a.y);
            Vt[(d0 + 2) * 36 + (rp ^ (((d0 + 2) >> 3) & 7))] = packh(bq.z, a.z);
            Vt[(d0 + 3) * 36 + (rp ^ (((d0 + 3) >> 3) & 7))] = packh(bq.w, a.w);
        }
        if (tid < 64) Msk[tid] = mb[t + tid] ? -1e30f : 0.f;
        __syncthreads();

        // ---- S = Q @ K^T : B-frags via ldmatrix.x4 ----
        float s[8][4] = {};
        #pragma unroll
        for (int j = 0; j < 8; ++j) {
            unsigned kf[8];
            const unsigned rowad = kwB + (unsigned)((j * 8 + l7) * 144 + (lane >> 3) * 16);
            ldsm4(kf[0], kf[1], kf[2], kf[3], rowad);
            ldsm4(kf[4], kf[5], kf[6], kf[7], rowad + 64);
            #pragma unroll
            for (int kk = 0; kk < 4; ++kk)
                mma_f16(s[j], qa[kk][0], qa[kk][1], qa[kk][2], qa[kk][3],
                        kf[2 * kk], kf[2 * kk + 1]);
        }

        // ---- scale(log2) + mask + online softmax ----
        float vm0 = -1e30f, vm1 = -1e30f;
        #pragma unroll
        for (int j = 0; j < 8; ++j) {
            const float mk0 = Msk[j * 8 + 2 * c];
            const float mk1 = Msk[j * 8 + 2 * c + 1];
            s[j][0] = fmaf(s[j][0], SCALE_L2E, mk0);
            s[j][1] = fmaf(s[j][1], SCALE_L2E, mk1);
            s[j][2] = fmaf(s[j][2], SCALE_L2E, mk0);
            s[j][3] = fmaf(s[j][3], SCALE_L2E, mk1);
            vm0 = fmaxf(vm0, fmaxf(s[j][0], s[j][1]));
            vm1 = fmaxf(vm1, fmaxf(s[j][2], s[j][3]));
        }
        vm0 = fmaxf(vm0, __shfl_xor_sync(0xffffffffu, vm0, 1));
        vm0 = fmaxf(vm0, __shfl_xor_sync(0xffffffffu, vm0, 2));
        vm1 = fmaxf(vm1, __shfl_xor_sync(0xffffffffu, vm1, 1));
        vm1 = fmaxf(vm1, __shfl_xor_sync(0xffffffffu, vm1, 2));

        const float mn0 = fmaxf(mr0, vm0);
        const float mn1 = fmaxf(mr1, vm1);
        const float cr0 = ex2(mr0 - mn0);
        const float cr1 = ex2(mr1 - mn1);
        mr0 = mn0; mr1 = mn1;

        // p = 2^(s - mn) computed pairwise in f16x2; results are PV A-frag words
        unsigned ph0[8], ph1[8];
        #pragma unroll
        for (int j = 0; j < 8; ++j) {
            ph0[j] = hex2(packh(s[j][1] - mn0, s[j][0] - mn0));
            ph1[j] = hex2(packh(s[j][3] - mn1, s[j][2] - mn1));
        }

        #pragma unroll
        for (int j = 0; j < 8; ++j) {
            o[j][0] *= cr0; o[j][1] *= cr0;
            o[j][2] *= cr1; o[j][3] *= cr1;
        }
        lacc[0] *= cr0; lacc[1] *= cr0;
        lacc[2] *= cr1; lacc[3] *= cr1;

        // ---- O += P @ V ; l += P @ 1 ----
        #pragma unroll
        for (int kk = 0; kk < 4; ++kk) {
            const unsigned pa0 = ph0[2 * kk];
            const unsigned pa1 = ph1[2 * kk];
            const unsigned pa2 = ph0[2 * kk + 1];
            const unsigned pa3 = ph1[2 * kk + 1];
            #pragma unroll
            for (int j = 0; j < 8; ++j) {
                const unsigned b0 = Vt[(j * 8 + g) * 36 + ((kk * 8 + c    ) ^ j)];
                const unsigned b1 = Vt[(j * 8 + g) * 36 + ((kk * 8 + c + 4) ^ j)];
                mma_f16(o[j], pa0, pa1, pa2, pa3, b0, b1);
            }
            mma_f16(lacc, pa0, pa1, pa2, pa3, HONE, HONE);
        }
    }

    // ---- normalize + write to [B,N,512] ----
    const float inv0 = 1.f / lacc[0];
    const float inv1 = 1.f / lacc[2];
    float* ob = g_o + ((size_t)(b * Nq) + n0 + w * 16) * DEC + h * 64;
    #pragma unroll
    for (int j = 0; j < 8; ++j) {
        float2 v0 = {o[j][0] * inv0, o[j][1] * inv0};
        float2 v1 = {o[j][2] * inv1, o[j][3] * inv1};
        *(float2*)(ob + (size_t)g * DEC + j * 8 + 2 * c)       = v0;
        *(float2*)(ob + (size_t)(g + 8) * DEC + j * 8 + 2 * c) = v1;
    }
}

// ---------------------------------------------------------------------------
extern "C" void kernel_launch(void* const* d_in, const int* in_sizes, int n_in,
                              void* d_out, int out_size)
{
    (void)in_sizes; (void)n_in; (void)out_size;
    const float* x   = (const float*)d_in[0];
    const float* y   = (const float*)d_in[1];
    const int*   kpm = (const int*)d_in[2];     // bool mask promoted to int32
    const float* Wq  = (const float*)d_in[3];
    const float* Wkv = (const float*)d_in[4];
    const float* Wp  = (const float*)d_in[5];
    const float* bp  = (const float*)d_in[6];
    float* out = (float*)d_out;

    gemm_mma<0, DEC><<<dim3(DEC / 64, Bsz * Nq / 128), 256>>>(x, Wq, nullptr, nullptr);
    gemm_mma<1, ENC><<<dim3(2 * DEC / 64, Bsz * Nkv / 128), 256>>>(y, Wkv, nullptr, nullptr);
    attn_kernel<<<dim3(Nq / 128, Bsz * NH), 256>>>(kpm);
    gemm_mma<2, DEC><<<dim3(DEC / 64, Bsz * Nq / 128), 256>>>(nullptr, Wp, out, bp);
}

// round 11
// speedup vs baseline: 1.3604x; 1.1852x over previous
#include <cuda_runtime.h>

#define DI __device__ __forceinline__

namespace {
constexpr int Bsz = 2;
constexpr int Nq  = 4096;
constexpr int Nkv = 4096;
constexpr int ENC = 768;
constexpr int DEC = 512;
constexpr int NH  = 8;
constexpr int HD  = 64;
constexpr float SCALE_L2E = 0.125f * 1.4426950408889634f;  // SCALE * log2(e)
}

// Scratch (allocation-free: static device globals)
__device__ float g_q[(size_t)Bsz * NH * Nq  * HD];  // [B,H,N,64]
__device__ float g_k[(size_t)Bsz * NH * Nkv * HD];  // [B,H,Ny,64]
__device__ float g_v[(size_t)Bsz * NH * Nkv * HD];  // [B,H,Ny,64]
__device__ float g_o[(size_t)Bsz * Nq * DEC];       // [B,N,512]

DI unsigned packh(float hi, float lo) {    // word = {lo, hi} f16x2
    unsigned r;
    asm("cvt.rn.f16x2.f32 %0, %1, %2;" : "=r"(r) : "f"(hi), "f"(lo));
    return r;
}

DI float ex2(float x) {
    float r;
    asm("ex2.approx.ftz.f32 %0, %1;" : "=f"(r) : "f"(x));
    return r;
}

DI unsigned hex2(unsigned x) {             // ex2 on f16x2 pair
    unsigned r;
    asm("ex2.approx.f16x2 %0, %1;" : "=r"(r) : "r"(x));
    return r;
}

DI void mma_f16(float c[4], unsigned a0, unsigned a1, unsigned a2, unsigned a3,
                unsigned b0, unsigned b1) {
    asm volatile(
        "mma.sync.aligned.m16n8k16.row.col.f32.f16.f16.f32 "
        "{%0,%1,%2,%3}, {%4,%5,%6,%7}, {%8,%9}, {%0,%1,%2,%3};"
        : "+f"(c[0]), "+f"(c[1]), "+f"(c[2]), "+f"(c[3])
        : "r"(a0), "r"(a1), "r"(a2), "r"(a3), "r"(b0), "r"(b1));
}

DI void ldsm4(unsigned& r0, unsigned& r1, unsigned& r2, unsigned& r3, unsigned addr) {
    asm volatile("ldmatrix.sync.aligned.m8n8.x4.shared.b16 {%0,%1,%2,%3}, [%4];"
                 : "=r"(r0), "=r"(r1), "=r"(r2), "=r"(r3) : "r"(addr));
}

DI void ldsm4t(unsigned& r0, unsigned& r1, unsigned& r2, unsigned& r3, unsigned addr) {
    asm volatile("ldmatrix.sync.aligned.m8n8.x4.trans.shared.b16 {%0,%1,%2,%3}, [%4];"
                 : "=r"(r0), "=r"(r1), "=r"(r2), "=r"(r3) : "r"(addr));
}

// ---------------------------------------------------------------------------
// GEMM-NT, f16 m16n8k16, ldmatrix frags, register-prefetch (R10, passing).
// ---------------------------------------------------------------------------
template<int MODE, int K>
__global__ __launch_bounds__(256, 2) void gemm_mma(const float* __restrict__ A,
                                                   const float* __restrict__ Bw,
                                                   float* __restrict__ Cout,
                                                   const float* __restrict__ bias)
{
    __shared__ __align__(16) unsigned As[128 * 36];
    __shared__ __align__(16) unsigned Bs[64 * 36];

    const int tid  = threadIdx.x;
    const int w    = tid >> 5;
    const int lane = tid & 31;
    const int g    = lane >> 2;
    const int c    = lane & 3;
    const int m0   = blockIdx.y << 7;
    const int n0   = blockIdx.x << 6;

    const int arow = tid >> 3;
    const int ac4  = (tid & 7) << 2;
    const int aw   = (tid & 7) << 1;

    const float* Abase = (MODE == 2) ? g_o : A;
    const float* aptr = Abase + (size_t)(m0 + arow) * K + ac4;
    const float* bptr = Bw    + (size_t)(n0 + arow) * K + ac4;

    const unsigned asB = (unsigned)__cvta_generic_to_shared(As);
    const unsigned bsB = (unsigned)__cvta_generic_to_shared(Bs);
    const int l7 = lane & 7;

    float acc[8][4] = {};
    float4 fa[4], fb[2];

    #pragma unroll
    for (int u = 0; u < 4; ++u) fa[u] = *(const float4*)(aptr + (size_t)(32 * u) * K);
    #pragma unroll
    for (int u = 0; u < 2; ++u) fb[u] = *(const float4*)(bptr + (size_t)(32 * u) * K);

    for (int k0 = 0; k0 < K; k0 += 32) {
        __syncthreads();
        #pragma unroll
        for (int u = 0; u < 4; ++u) {
            uint2 p = {packh(fa[u].y, fa[u].x), packh(fa[u].w, fa[u].z)};
            *(uint2*)(As + (arow + 32 * u) * 36 + aw) = p;
        }
        #pragma unroll
        for (int u = 0; u < 2; ++u) {
            uint2 p = {packh(fb[u].y, fb[u].x), packh(fb[u].w, fb[u].z)};
            *(uint2*)(Bs + (arow + 32 * u) * 36 + aw) = p;
        }
        __syncthreads();

        if (k0 + 32 < K) {
            #pragma unroll
            for (int u = 0; u < 4; ++u)
                fa[u] = *(const float4*)(aptr + (size_t)(32 * u) * K + k0 + 32);
            #pragma unroll
            for (int u = 0; u < 2; ++u)
                fb[u] = *(const float4*)(bptr + (size_t)(32 * u) * K + k0 + 32);
        }

        unsigned a[2][4];
        #pragma unroll
        for (int kk = 0; kk < 2; ++kk) {
            unsigned ad = asB + (unsigned)((w * 16 + ((lane >> 3) & 1) * 8 + l7) * 144
                                           + (lane >> 4) * 16 + kk * 32);
            ldsm4(a[kk][0], a[kk][1], a[kk][2], a[kk][3], ad);
        }
        #pragma unroll
        for (int j = 0; j < 8; ++j) {
            unsigned bb[4];
            unsigned bd = bsB + (unsigned)((j * 8 + l7) * 144 + (lane >> 3) * 16);
            ldsm4(bb[0], bb[1], bb[2], bb[3], bd);
            mma_f16(acc[j], a[0][0], a[0][1], a[0][2], a[0][3], bb[0], bb[1]);
            mma_f16(acc[j], a[1][0], a[1][1], a[1][2], a[1][3], bb[2], bb[3]);
        }
    }

    #pragma unroll
    for (int j = 0; j < 8; ++j) {
        const int n = n0 + j * 8 + 2 * c;
        #pragma unroll
        for (int half = 0; half < 2; ++half) {
            const int m = m0 + w * 16 + g + half * 8;
            float2 val = {acc[j][2 * half], acc[j][2 * half + 1]};
            if (MODE == 0) {
                const int b = m >> 12, nn = m & 4095, h = n >> 6, d = n & 63;
                *(float2*)&g_q[(((size_t)(b * NH + h)) * Nq + nn) * HD + d] = val;
            } else if (MODE == 1) {
                const int b = m >> 12, nn = m & 4095;
                if (n < DEC) {
                    const int h = n >> 6, d = n & 63;
                    *(float2*)&g_k[(((size_t)(b * NH + h)) * Nkv + nn) * HD + d] = val;
                } else {
                    const int n2 = n - DEC, h = n2 >> 6, d = n2 & 63;
                    *(float2*)&g_v[(((size_t)(b * NH + h)) * Nkv + nn) * HD + d] = val;
                }
            } else {
                float2 bb = *(const float2*)&bias[n];
                val.x += bb.x; val.y += bb.y;
                *(float2*)&Cout[(size_t)m * DEC + n] = val;
            }
        }
    }
}

// ---------------------------------------------------------------------------
// Flash attention, f16 mma.m16n8k16.
// K AND V both stored row-major f16-pairs (stride 36 words = 144B).
// S  B-frags: ldmatrix.x4       on Kw rows (keys).
// PV B-frags: ldmatrix.x4.trans on Vw rows (keys) -> col-major V frags.
// exp via ex2.approx.f16x2 -> results ARE the PV A-frag words.
// Row sums via tensor core: P @ ones.
// ---------------------------------------------------------------------------
__global__ __launch_bounds__(256, 2) void attn_kernel(const int* __restrict__ kpm)
{
    __shared__ __align__(16) unsigned Kw[64 * 36];
    __shared__ __align__(16) unsigned Vw[64 * 36];
    __shared__ float Msk[64];

    const int tid  = threadIdx.x;
    const int w    = tid >> 5;
    const int lane = tid & 31;
    const int g    = lane >> 2;
    const int c    = lane & 3;
    const int l7   = lane & 7;
    const int bh   = blockIdx.y;
    const int b    = bh >> 3;
    const int h    = bh & 7;
    const int n0   = blockIdx.x << 7;

    const float* qb = g_q + ((size_t)bh * Nq + n0) * HD;
    const float* kb = g_k + (size_t)bh * Nkv * HD;
    const float* vb = g_v + (size_t)bh * Nkv * HD;
    const int*   mb = kpm + b * Nkv;

    const unsigned kwB = (unsigned)__cvta_generic_to_shared(Kw);
    const unsigned vwB = (unsigned)__cvta_generic_to_shared(Vw);
    const unsigned HONE = 0x3C003C00u;   // f16x2 {1.0, 1.0}

    // ---- Stage Q (128x64) as f16 pairs through Kw/Vw, pull A-frags ----
    #pragma unroll
    for (int u = 0; u < 8; ++u) {
        const int chunk = tid + 256 * u;
        const int row = chunk >> 4;
        const int c4  = (chunk & 15) << 2;
        float4 qv = *(const float4*)(qb + (size_t)row * HD + c4);
        uint2 qt = {packh(qv.y, qv.x), packh(qv.w, qv.z)};
        unsigned* base = (row < 64) ? Kw : Vw;
        *(uint2*)(base + (row & 63) * 36 + (c4 >> 1)) = qt;
    }
    __syncthreads();

    unsigned qa[4][4];
    {
        const unsigned* Qb = (w < 4) ? Kw : Vw;
        const int rb = (w * 16) & 63;
        #pragma unroll
        for (int kk = 0; kk < 4; ++kk) {
            qa[kk][0] = Qb[(rb + g    ) * 36 + kk * 8 + c];
            qa[kk][1] = Qb[(rb + g + 8) * 36 + kk * 8 + c];
            qa[kk][2] = Qb[(rb + g    ) * 36 + kk * 8 + c + 4];
            qa[kk][3] = Qb[(rb + g + 8) * 36 + kk * 8 + c + 4];
        }
    }

    float o[8][4] = {};
    float lacc[4] = {};
    float mr0 = -1e30f, mr1 = -1e30f;

    // ldmatrix address components (per thread, loop-invariant)
    const unsigned krow8 = ((lane >> 3) & 1) * 8 + l7;   // row within 16-key block
    const unsigned jhalf = (lane >> 4);                  // 0/1 -> +8 dims or +16B

    for (int t = 0; t < Nkv; t += 64) {
        __syncthreads();   // prior-iter smem reads complete before restaging

        // ---- stage K and V, both row-major f16 pairs ----
        #pragma unroll
        for (int u = 0; u < 4; ++u) {
            const int chunk = tid + 256 * u;
            const int row = chunk >> 4;
            const int c4  = (chunk & 15) << 2;
            float4 kv = *(const float4*)(kb + (size_t)(t + row) * HD + c4);
            *(uint2*)(Kw + row * 36 + (c4 >> 1)) =
                uint2{packh(kv.y, kv.x), packh(kv.w, kv.z)};
            float4 vv = *(const float4*)(vb + (size_t)(t + row) * HD + c4);
            *(uint2*)(Vw + row * 36 + (c4 >> 1)) =
                uint2{packh(vv.y, vv.x), packh(vv.w, vv.z)};
        }
        if (tid < 64) Msk[tid] = mb[t + tid] ? -1e30f : 0.f;
        __syncthreads();

        // ---- S = Q @ K^T : B-frags via ldmatrix.x4 ----
        float s[8][4] = {};
        #pragma unroll
        for (int j = 0; j < 8; ++j) {
            unsigned kf[8];
            const unsigned rowad = kwB + (unsigned)((j * 8 + l7) * 144 + (lane >> 3) * 16);
            ldsm4(kf[0], kf[1], kf[2], kf[3], rowad);
            ldsm4(kf[4], kf[5], kf[6], kf[7], rowad + 64);
            #pragma unroll
            for (int kk = 0; kk < 4; ++kk)
                mma_f16(s[j], qa[kk][0], qa[kk][1], qa[kk][2], qa[kk][3],
                        kf[2 * kk], kf[2 * kk + 1]);
        }

        // ---- scale(log2) + mask + online softmax ----
        float vm0 = -1e30f, vm1 = -1e30f;
        #pragma unroll
        for (int j = 0; j < 8; ++j) {
            const float mk0 = Msk[j * 8 + 2 * c];
            const float mk1 = Msk[j * 8 + 2 * c + 1];
            s[j][0] = fmaf(s[j][0], SCALE_L2E, mk0);
            s[j][1] = fmaf(s[j][1], SCALE_L2E, mk1);
            s[j][2] = fmaf(s[j][2], SCALE_L2E, mk0);
            s[j][3] = fmaf(s[j][3], SCALE_L2E, mk1);
            vm0 = fmaxf(vm0, fmaxf(s[j][0], s[j][1]));
            vm1 = fmaxf(vm1, fmaxf(s[j][2], s[j][3]));
        }
        vm0 = fmaxf(vm0, __shfl_xor_sync(0xffffffffu, vm0, 1));
        vm0 = fmaxf(vm0, __shfl_xor_sync(0xffffffffu, vm0, 2));
        vm1 = fmaxf(vm1, __shfl_xor_sync(0xffffffffu, vm1, 1));
        vm1 = fmaxf(vm1, __shfl_xor_sync(0xffffffffu, vm1, 2));

        const float mn0 = fmaxf(mr0, vm0);
        const float mn1 = fmaxf(mr1, vm1);
        const float cr0 = ex2(mr0 - mn0);
        const float cr1 = ex2(mr1 - mn1);
        mr0 = mn0; mr1 = mn1;

        unsigned ph0[8], ph1[8];
        #pragma unroll
        for (int j = 0; j < 8; ++j) {
            ph0[j] = hex2(packh(s[j][1] - mn0, s[j][0] - mn0));
            ph1[j] = hex2(packh(s[j][3] - mn1, s[j][2] - mn1));
        }

        #pragma unroll
        for (int j = 0; j < 8; ++j) {
            o[j][0] *= cr0; o[j][1] *= cr0;
            o[j][2] *= cr1; o[j][3] *= cr1;
        }
        lacc[0] *= cr0; lacc[1] *= cr0;
        lacc[2] *= cr1; lacc[3] *= cr1;

        // ---- O += P @ V (ldsm.trans B-frags) ; l += P @ 1 ----
        #pragma unroll
        for (int kk = 0; kk < 4; ++kk) {
            const unsigned pa0 = ph0[2 * kk];
            const unsigned pa1 = ph1[2 * kk];
            const unsigned pa2 = ph0[2 * kk + 1];
            const unsigned pa3 = ph1[2 * kk + 1];
            #pragma unroll
            for (int jp = 0; jp < 8; jp += 2) {
                unsigned b0, b1, b2, b3;
                const unsigned vad = vwB +
                    (unsigned)((16 * kk + krow8) * 144 + (jp + jhalf) * 16);
                ldsm4t(b0, b1, b2, b3, vad);
                mma_f16(o[jp],     pa0, pa1, pa2, pa3, b0, b1);
                mma_f16(o[jp + 1], pa0, pa1, pa2, pa3, b2, b3);
            }
            mma_f16(lacc, pa0, pa1, pa2, pa3, HONE, HONE);
        }
    }

    // ---- normalize + write to [B,N,512] ----
    const float inv0 = 1.f / lacc[0];
    const float inv1 = 1.f / lacc[2];
    float* ob = g_o + ((size_t)(b * Nq) + n0 + w * 16) * DEC + h * 64;
    #pragma unroll
    for (int j = 0; j < 8; ++j) {
        float2 v0 = {o[j][0] * inv0, o[j][1] * inv0};
        float2 v1 = {o[j][2] * inv1, o[j][3] * inv1};
        *(float2*)(ob + (size_t)g * DEC + j * 8 + 2 * c)       = v0;
        *(float2*)(ob + (size_t)(g + 8) * DEC + j * 8 + 2 * c) = v1;
    }
}

// ---------------------------------------------------------------------------
extern "C" void kernel_launch(void* const* d_in, const int* in_sizes, int n_in,
                              void* d_out, int out_size)
{
    (void)in_sizes; (void)n_in; (void)out_size;
    const float* x   = (const float*)d_in[0];
    const float* y   = (const float*)d_in[1];
    const int*   kpm = (const int*)d_in[2];     // bool mask promoted to int32
    const float* Wq  = (const float*)d_in[3];
    const float* Wkv = (const float*)d_in[4];
    const float* Wp  = (const float*)d_in[5];
    const float* bp  = (const float*)d_in[6];
    float* out = (float*)d_out;

    gemm_mma<0, DEC><<<dim3(DEC / 64, Bsz * Nq / 128), 256>>>(x, Wq, nullptr, nullptr);
    gemm_mma<1, ENC><<<dim3(2 * DEC / 64, Bsz * Nkv / 128), 256>>>(y, Wkv, nullptr, nullptr);
    attn_kernel<<<dim3(Nq / 128, Bsz * NH), 256>>>(kpm);
    gemm_mma<2, DEC><<<dim3(DEC / 64, Bsz * Nq / 128), 256>>>(nullptr, Wp, out, bp);
}

// round 12
// speedup vs baseline: 1.4515x; 1.0670x over previous
#include <cuda_runtime.h>

#define DI __device__ __forceinline__

namespace {
constexpr int Bsz = 2;
constexpr int Nq  = 4096;
constexpr int Nkv = 4096;
constexpr int ENC = 768;
constexpr int DEC = 512;
constexpr int NH  = 8;
constexpr int HD  = 64;
constexpr float SCALE_L2E = 0.125f * 1.4426950408889634f;  // SCALE * log2(e)
}

// Scratch (allocation-free). q/k/v stored as packed f16x2 words (32 words/row).
__device__ unsigned g_qh[(size_t)Bsz * NH * Nq  * 32];
__device__ unsigned g_kh[(size_t)Bsz * NH * Nkv * 32];
__device__ unsigned g_vh[(size_t)Bsz * NH * Nkv * 32];
__device__ float    g_o [(size_t)Bsz * Nq * DEC];

DI unsigned packh(float hi, float lo) {    // word = {lo, hi} f16x2
    unsigned r;
    asm("cvt.rn.f16x2.f32 %0, %1, %2;" : "=r"(r) : "f"(hi), "f"(lo));
    return r;
}

DI float ex2(float x) {
    float r;
    asm("ex2.approx.ftz.f32 %0, %1;" : "=f"(r) : "f"(x));
    return r;
}

DI unsigned hex2(unsigned x) {             // ex2 on f16x2 pair
    unsigned r;
    asm("ex2.approx.f16x2 %0, %1;" : "=r"(r) : "r"(x));
    return r;
}

DI void mma_f16(float c[4], unsigned a0, unsigned a1, unsigned a2, unsigned a3,
                unsigned b0, unsigned b1) {
    asm volatile(
        "mma.sync.aligned.m16n8k16.row.col.f32.f16.f16.f32 "
        "{%0,%1,%2,%3}, {%4,%5,%6,%7}, {%8,%9}, {%0,%1,%2,%3};"
        : "+f"(c[0]), "+f"(c[1]), "+f"(c[2]), "+f"(c[3])
        : "r"(a0), "r"(a1), "r"(a2), "r"(a3), "r"(b0), "r"(b1));
}

DI void ldsm4(unsigned& r0, unsigned& r1, unsigned& r2, unsigned& r3, unsigned addr) {
    asm volatile("ldmatrix.sync.aligned.m8n8.x4.shared.b16 {%0,%1,%2,%3}, [%4];"
                 : "=r"(r0), "=r"(r1), "=r"(r2), "=r"(r3) : "r"(addr));
}

DI void ldsm4t(unsigned& r0, unsigned& r1, unsigned& r2, unsigned& r3, unsigned addr) {
    asm volatile("ldmatrix.sync.aligned.m8n8.x4.trans.shared.b16 {%0,%1,%2,%3}, [%4];"
                 : "=r"(r0), "=r"(r1), "=r"(r2), "=r"(r3) : "r"(addr));
}

DI void cp16(unsigned dst, const void* src) {
    asm volatile("cp.async.cg.shared.global [%0], [%1], 16;" :: "r"(dst), "l"(src));
}
DI void cp_commit() { asm volatile("cp.async.commit_group;"); }
DI void cp_wait0()  { asm volatile("cp.async.wait_group 0;"); }

// ---------------------------------------------------------------------------
// GEMM-NT, f16 m16n8k16 (R10/R11 passing core); MODE 0/1 epilogues now pack
// results to f16x2 global buffers.
// ---------------------------------------------------------------------------
template<int MODE, int K>
__global__ __launch_bounds__(256, 2) void gemm_mma(const float* __restrict__ A,
                                                   const float* __restrict__ Bw,
                                                   float* __restrict__ Cout,
                                                   const float* __restrict__ bias)
{
    __shared__ __align__(16) unsigned As[128 * 36];
    __shared__ __align__(16) unsigned Bs[64 * 36];

    const int tid  = threadIdx.x;
    const int w    = tid >> 5;
    const int lane = tid & 31;
    const int g    = lane >> 2;
    const int c    = lane & 3;
    const int m0   = blockIdx.y << 7;
    const int n0   = blockIdx.x << 6;

    const int arow = tid >> 3;
    const int ac4  = (tid & 7) << 2;
    const int aw   = (tid & 7) << 1;

    const float* Abase = (MODE == 2) ? g_o : A;
    const float* aptr = Abase + (size_t)(m0 + arow) * K + ac4;
    const float* bptr = Bw    + (size_t)(n0 + arow) * K + ac4;

    const unsigned asB = (unsigned)__cvta_generic_to_shared(As);
    const unsigned bsB = (unsigned)__cvta_generic_to_shared(Bs);
    const int l7 = lane & 7;

    float acc[8][4] = {};
    float4 fa[4], fb[2];

    #pragma unroll
    for (int u = 0; u < 4; ++u) fa[u] = *(const float4*)(aptr + (size_t)(32 * u) * K);
    #pragma unroll
    for (int u = 0; u < 2; ++u) fb[u] = *(const float4*)(bptr + (size_t)(32 * u) * K);

    for (int k0 = 0; k0 < K; k0 += 32) {
        __syncthreads();
        #pragma unroll
        for (int u = 0; u < 4; ++u) {
            uint2 p = {packh(fa[u].y, fa[u].x), packh(fa[u].w, fa[u].z)};
            *(uint2*)(As + (arow + 32 * u) * 36 + aw) = p;
        }
        #pragma unroll
        for (int u = 0; u < 2; ++u) {
            uint2 p = {packh(fb[u].y, fb[u].x), packh(fb[u].w, fb[u].z)};
            *(uint2*)(Bs + (arow + 32 * u) * 36 + aw) = p;
        }
        __syncthreads();

        if (k0 + 32 < K) {
            #pragma unroll
            for (int u = 0; u < 4; ++u)
                fa[u] = *(const float4*)(aptr + (size_t)(32 * u) * K + k0 + 32);
            #pragma unroll
            for (int u = 0; u < 2; ++u)
                fb[u] = *(const float4*)(bptr + (size_t)(32 * u) * K + k0 + 32);
        }

        unsigned a[2][4];
        #pragma unroll
        for (int kk = 0; kk < 2; ++kk) {
            unsigned ad = asB + (unsigned)((w * 16 + ((lane >> 3) & 1) * 8 + l7) * 144
                                           + (lane >> 4) * 16 + kk * 32);
            ldsm4(a[kk][0], a[kk][1], a[kk][2], a[kk][3], ad);
        }
        #pragma unroll
        for (int j = 0; j < 8; ++j) {
            unsigned bb[4];
            unsigned bd = bsB + (unsigned)((j * 8 + l7) * 144 + (lane >> 3) * 16);
            ldsm4(bb[0], bb[1], bb[2], bb[3], bd);
            mma_f16(acc[j], a[0][0], a[0][1], a[0][2], a[0][3], bb[0], bb[1]);
            mma_f16(acc[j], a[1][0], a[1][1], a[1][2], a[1][3], bb[2], bb[3]);
        }
    }

    #pragma unroll
    for (int j = 0; j < 8; ++j) {
        const int n = n0 + j * 8 + 2 * c;
        #pragma unroll
        for (int half = 0; half < 2; ++half) {
            const int m = m0 + w * 16 + g + half * 8;
            float2 val = {acc[j][2 * half], acc[j][2 * half + 1]};
            if (MODE == 0) {
                const int b = m >> 12, nn = m & 4095, h = n >> 6, d = n & 63;
                g_qh[(((size_t)(b * NH + h)) * Nq + nn) * 32 + (d >> 1)] =
                    packh(val.y, val.x);
            } else if (MODE == 1) {
                const int b = m >> 12, nn = m & 4095;
                if (n < DEC) {
                    const int h = n >> 6, d = n & 63;
                    g_kh[(((size_t)(b * NH + h)) * Nkv + nn) * 32 + (d >> 1)] =
                        packh(val.y, val.x);
                } else {
                    const int n2 = n - DEC, h = n2 >> 6, d = n2 & 63;
                    g_vh[(((size_t)(b * NH + h)) * Nkv + nn) * 32 + (d >> 1)] =
                        packh(val.y, val.x);
                }
            } else {
                float2 bb = *(const float2*)&bias[n];
                val.x += bb.x; val.y += bb.y;
                *(float2*)&Cout[(size_t)m * DEC + n] = val;
            }
        }
    }
}

// ---------------------------------------------------------------------------
// Flash attention, f16 mma.m16n8k16, cp.async double-buffered KV staging.
// K/V already f16x2 in global -> staging is pure 16B LDGSTS (no regs/packs).
// One __syncthreads per tile; tile t+1 loads overlap tile t compute.
// ---------------------------------------------------------------------------
__global__ __launch_bounds__(256, 2) void attn_kernel(const int* __restrict__ kpm)
{
    __shared__ __align__(16) unsigned KV[2][2][64 * 36];   // [stage][K/V]
    __shared__ __align__(16) int MskI[2][64];

    const int tid  = threadIdx.x;
    const int w    = tid >> 5;
    const int lane = tid & 31;
    const int g    = lane >> 2;
    const int c    = lane & 3;
    const int l7   = lane & 7;
    const int bh   = blockIdx.y;
    const int b    = bh >> 3;
    const int h    = bh & 7;
    const int n0   = blockIdx.x << 7;

    const unsigned* qb = g_qh + ((size_t)bh * Nq + n0) * 32;
    const unsigned* kb = g_kh + (size_t)bh * Nkv * 32;
    const unsigned* vb = g_vh + (size_t)bh * Nkv * 32;
    const int*      mb = kpm + b * Nkv;

    unsigned kB[2], vB[2], mB[2];
    #pragma unroll
    for (int p = 0; p < 2; ++p) {
        kB[p] = (unsigned)__cvta_generic_to_shared(&KV[p][0][0]);
        vB[p] = (unsigned)__cvta_generic_to_shared(&KV[p][1][0]);
        mB[p] = (unsigned)__cvta_generic_to_shared(&MskI[p][0]);
    }
    const unsigned HONE = 0x3C003C00u;   // f16x2 {1.0, 1.0}

    // staging coordinates: 2 chunks of 16B per matrix per thread
    const int srow0 = tid >> 3, scol = (tid & 7) * 4;            // chunk tid
    const int srow1 = (tid + 256) >> 3;                          // chunk tid+256

    // ---- prologue: stage tile 0 ----
    {
        cp16(kB[0] + srow0 * 144 + scol * 4, kb + (size_t)srow0 * 32 + scol);
        cp16(kB[0] + srow1 * 144 + scol * 4, kb + (size_t)srow1 * 32 + scol);
        cp16(vB[0] + srow0 * 144 + scol * 4, vb + (size_t)srow0 * 32 + scol);
        cp16(vB[0] + srow1 * 144 + scol * 4, vb + (size_t)srow1 * 32 + scol);
        if (tid < 16) cp16(mB[0] + tid * 16, mb + tid * 4);
        cp_commit();
    }

    // ---- Q A-frags straight from global (one-time) ----
    unsigned qa[4][4];
    {
        const unsigned* q0 = qb + (size_t)(w * 16 + g) * 32;
        const unsigned* q1 = q0 + 8 * 32;
        #pragma unroll
        for (int kk = 0; kk < 4; ++kk) {
            qa[kk][0] = q0[kk * 8 + c];
            qa[kk][1] = q1[kk * 8 + c];
            qa[kk][2] = q0[kk * 8 + c + 4];
            qa[kk][3] = q1[kk * 8 + c + 4];
        }
    }

    float o[8][4] = {};
    float lacc[4] = {};
    float mr0 = -1e30f, mr1 = -1e30f;

    const unsigned krow8 = ((lane >> 3) & 1) * 8 + l7;   // PV ldsm row within 16
    const unsigned jhalf = (lane >> 4);

    for (int it = 0; it < Nkv / 64; ++it) {
        const int p = it & 1;
        cp_wait0();
        __syncthreads();   // all cp.async writes visible; all warps done with buf p^1

        if (it + 1 < Nkv / 64) {   // stage tile it+1 into buf p^1 (overlaps compute)
            const int t1 = (it + 1) * 64;
            const unsigned* kt = kb + (size_t)t1 * 32;
            const unsigned* vt = vb + (size_t)t1 * 32;
            cp16(kB[p ^ 1] + srow0 * 144 + scol * 4, kt + (size_t)srow0 * 32 + scol);
            cp16(kB[p ^ 1] + srow1 * 144 + scol * 4, kt + (size_t)srow1 * 32 + scol);
            cp16(vB[p ^ 1] + srow0 * 144 + scol * 4, vt + (size_t)srow0 * 32 + scol);
            cp16(vB[p ^ 1] + srow1 * 144 + scol * 4, vt + (size_t)srow1 * 32 + scol);
            if (tid < 16) cp16(mB[p ^ 1] + tid * 16, mb + t1 + tid * 4);
        }
        cp_commit();

        // ---- S = Q @ K^T : B-frags via ldmatrix.x4 ----
        float s[8][4] = {};
        #pragma unroll
        for (int j = 0; j < 8; ++j) {
            unsigned kf[8];
            const unsigned rowad = kB[p] + (unsigned)((j * 8 + l7) * 144 + (lane >> 3) * 16);
            ldsm4(kf[0], kf[1], kf[2], kf[3], rowad);
            ldsm4(kf[4], kf[5], kf[6], kf[7], rowad + 64);
            #pragma unroll
            for (int kk = 0; kk < 4; ++kk)
                mma_f16(s[j], qa[kk][0], qa[kk][1], qa[kk][2], qa[kk][3],
                        kf[2 * kk], kf[2 * kk + 1]);
        }

        // ---- scale(log2) + mask + online softmax ----
        const int* mi = MskI[p];
        float vm0 = -1e30f, vm1 = -1e30f;
        #pragma unroll
        for (int j = 0; j < 8; ++j) {
            const float mk0 = mi[j * 8 + 2 * c]     ? -1e30f : 0.f;
            const float mk1 = mi[j * 8 + 2 * c + 1] ? -1e30f : 0.f;
            s[j][0] = fmaf(s[j][0], SCALE_L2E, mk0);
            s[j][1] = fmaf(s[j][1], SCALE_L2E, mk1);
            s[j][2] = fmaf(s[j][2], SCALE_L2E, mk0);
            s[j][3] = fmaf(s[j][3], SCALE_L2E, mk1);
            vm0 = fmaxf(vm0, fmaxf(s[j][0], s[j][1]));
            vm1 = fmaxf(vm1, fmaxf(s[j][2], s[j][3]));
        }
        vm0 = fmaxf(vm0, __shfl_xor_sync(0xffffffffu, vm0, 1));
        vm0 = fmaxf(vm0, __shfl_xor_sync(0xffffffffu, vm0, 2));
        vm1 = fmaxf(vm1, __shfl_xor_sync(0xffffffffu, vm1, 1));
        vm1 = fmaxf(vm1, __shfl_xor_sync(0xffffffffu, vm1, 2));

        const float mn0 = fmaxf(mr0, vm0);
        const float mn1 = fmaxf(mr1, vm1);
        const float cr0 = ex2(mr0 - mn0);
        const float cr1 = ex2(mr1 - mn1);
        mr0 = mn0; mr1 = mn1;

        unsigned ph0[8], ph1[8];
        #pragma unroll
        for (int j = 0; j < 8; ++j) {
            ph0[j] = hex2(packh(s[j][1] - mn0, s[j][0] - mn0));
            ph1[j] = hex2(packh(s[j][3] - mn1, s[j][2] - mn1));
        }

        #pragma unroll
        for (int j = 0; j < 8; ++j) {
            o[j][0] *= cr0; o[j][1] *= cr0;
            o[j][2] *= cr1; o[j][3] *= cr1;
        }
        lacc[0] *= cr0; lacc[1] *= cr0;
        lacc[2] *= cr1; lacc[3] *= cr1;

        // ---- O += P @ V (ldsm.trans B-frags) ; l += P @ 1 ----
        #pragma unroll
        for (int kk = 0; kk < 4; ++kk) {
            const unsigned pa0 = ph0[2 * kk];
            const unsigned pa1 = ph1[2 * kk];
            const unsigned pa2 = ph0[2 * kk + 1];
            const unsigned pa3 = ph1[2 * kk + 1];
            #pragma unroll
            for (int jp = 0; jp < 8; jp += 2) {
                unsigned b0, b1, b2, b3;
                const unsigned vad = vB[p] +
                    (unsigned)((16 * kk + krow8) * 144 + (jp + jhalf) * 16);
                ldsm4t(b0, b1, b2, b3, vad);
                mma_f16(o[jp],     pa0, pa1, pa2, pa3, b0, b1);
                mma_f16(o[jp + 1], pa0, pa1, pa2, pa3, b2, b3);
            }
            mma_f16(lacc, pa0, pa1, pa2, pa3, HONE, HONE);
        }
    }

    // ---- normalize + write to [B,N,512] ----
    const float inv0 = 1.f / lacc[0];
    const float inv1 = 1.f / lacc[2];
    float* ob = g_o + ((size_t)(b * Nq) + n0 + w * 16) * DEC + h * 64;
    #pragma unroll
    for (int j = 0; j < 8; ++j) {
        float2 v0 = {o[j][0] * inv0, o[j][1] * inv0};
        float2 v1 = {o[j][2] * inv1, o[j][3] * inv1};
        *(float2*)(ob + (size_t)g * DEC + j * 8 + 2 * c)       = v0;
        *(float2*)(ob + (size_t)(g + 8) * DEC + j * 8 + 2 * c) = v1;
    }
}

// ---------------------------------------------------------------------------
extern "C" void kernel_launch(void* const* d_in, const int* in_sizes, int n_in,
                              void* d_out, int out_size)
{
    (void)in_sizes; (void)n_in; (void)out_size;
    const float* x   = (const float*)d_in[0];
    const float* y   = (const float*)d_in[1];
    const int*   kpm = (const int*)d_in[2];     // bool mask promoted to int32
    const float* Wq  = (const float*)d_in[3];
    const float* Wkv = (const float*)d_in[4];
    const float* Wp  = (const float*)d_in[5];
    const float* bp  = (const float*)d_in[6];
    float* out = (float*)d_out;

    gemm_mma<0, DEC><<<dim3(DEC / 64, Bsz * Nq / 128), 256>>>(x, Wq, nullptr, nullptr);
    gemm_mma<1, ENC><<<dim3(2 * DEC / 64, Bsz * Nkv / 128), 256>>>(y, Wkv, nullptr, nullptr);
    attn_kernel<<<dim3(Nq / 128, Bsz * NH), 256>>>(kpm);
    gemm_mma<2, DEC><<<dim3(DEC / 64, Bsz * Nq / 128), 256>>>(nullptr, Wp, out, bp);
}

// round 13
// speedup vs baseline: 1.5341x; 1.0569x over previous
#include <cuda_runtime.h>

#define DI __device__ __forceinline__

namespace {
constexpr int Bsz = 2;
constexpr int Nq  = 4096;
constexpr int Nkv = 4096;
constexpr int ENC = 768;
constexpr int DEC = 512;
constexpr int NH  = 8;
constexpr int HD  = 64;
constexpr float SCALE_L2E = 0.125f * 1.4426950408889634f;  // SCALE * log2(e)
}

// Scratch (allocation-free). All f16 tensors stored as packed f16x2 words.
__device__ __align__(16) unsigned g_qh [(size_t)Bsz * NH * Nq  * 32];
__device__ __align__(16) unsigned g_kh [(size_t)Bsz * NH * Nkv * 32];
__device__ __align__(16) unsigned g_vh [(size_t)Bsz * NH * Nkv * 32];
__device__ __align__(16) unsigned g_oh [(size_t)Bsz * Nq * (DEC / 2)];
__device__ __align__(16) unsigned g_xh [(size_t)Bsz * Nq  * (DEC / 2)];
__device__ __align__(16) unsigned g_yh [(size_t)Bsz * Nkv * (ENC / 2)];
__device__ __align__(16) unsigned g_wqh [(size_t)DEC * (DEC / 2)];
__device__ __align__(16) unsigned g_wkvh[(size_t)2 * DEC * (ENC / 2)];
__device__ __align__(16) unsigned g_wph [(size_t)DEC * (DEC / 2)];

DI unsigned packh(float hi, float lo) {    // word = {lo, hi} f16x2
    unsigned r;
    asm("cvt.rn.f16x2.f32 %0, %1, %2;" : "=r"(r) : "f"(hi), "f"(lo));
    return r;
}

DI float ex2(float x) {
    float r;
    asm("ex2.approx.ftz.f32 %0, %1;" : "=f"(r) : "f"(x));
    return r;
}

DI unsigned hex2(unsigned x) {             // ex2 on f16x2 pair
    unsigned r;
    asm("ex2.approx.f16x2 %0, %1;" : "=r"(r) : "r"(x));
    return r;
}

DI void mma_f16(float c[4], unsigned a0, unsigned a1, unsigned a2, unsigned a3,
                unsigned b0, unsigned b1) {
    asm volatile(
        "mma.sync.aligned.m16n8k16.row.col.f32.f16.f16.f32 "
        "{%0,%1,%2,%3}, {%4,%5,%6,%7}, {%8,%9}, {%0,%1,%2,%3};"
        : "+f"(c[0]), "+f"(c[1]), "+f"(c[2]), "+f"(c[3])
        : "r"(a0), "r"(a1), "r"(a2), "r"(a3), "r"(b0), "r"(b1));
}

DI void ldsm4(unsigned& r0, unsigned& r1, unsigned& r2, unsigned& r3, unsigned addr) {
    asm volatile("ldmatrix.sync.aligned.m8n8.x4.shared.b16 {%0,%1,%2,%3}, [%4];"
                 : "=r"(r0), "=r"(r1), "=r"(r2), "=r"(r3) : "r"(addr));
}

DI void ldsm4t(unsigned& r0, unsigned& r1, unsigned& r2, unsigned& r3, unsigned addr) {
    asm volatile("ldmatrix.sync.aligned.m8n8.x4.trans.shared.b16 {%0,%1,%2,%3}, [%4];"
                 : "=r"(r0), "=r"(r1), "=r"(r2), "=r"(r3) : "r"(addr));
}

DI void cp16(unsigned dst, const void* src) {
    asm volatile("cp.async.cg.shared.global [%0], [%1], 16;" :: "r"(dst), "l"(src));
}
DI void cp_commit() { asm volatile("cp.async.commit_group;"); }
DI void cp_wait0()  { asm volatile("cp.async.wait_group 0;"); }

// ---------------------------------------------------------------------------
// f32 -> packed f16x2 conversion (one-time, memory-bound)
// T: 0=x->g_xh 1=y->g_yh 2=Wq->g_wqh 3=Wkv->g_wkvh 4=Wp->g_wph
// ---------------------------------------------------------------------------
template<int T>
__global__ void cvt_f16(const float4* __restrict__ src, int n4)
{
    const int i = blockIdx.x * blockDim.x + threadIdx.x;
    if (i >= n4) return;
    uint2* dst = (T == 0) ? (uint2*)g_xh  : (T == 1) ? (uint2*)g_yh
               : (T == 2) ? (uint2*)g_wqh : (T == 3) ? (uint2*)g_wkvh
               : (uint2*)g_wph;
    float4 v = src[i];
    dst[i] = uint2{packh(v.y, v.x), packh(v.w, v.z)};
}

// ---------------------------------------------------------------------------
// GEMM-NT, f16 m16n8k16, cp.async double-buffered staging.
// A,B f16x2 in global. BM=128, BN=64, BK=32 (16 words). Row stride 20 words
// (80B = 5x16B, 5 coprime 8 -> ldmatrix conflict-free). One sync per chunk.
// MODE 0: g_xh @ g_wqh -> g_qh ; MODE 1: g_yh @ g_wkvh -> g_kh/g_vh ;
// MODE 2: g_oh @ g_wph -> out + bias
// ---------------------------------------------------------------------------
template<int MODE, int K>
__global__ __launch_bounds__(256, 2) void gemm_mma(float* __restrict__ Cout,
                                                   const float* __restrict__ bias)
{
    constexpr int KW = K / 2;            // words per row
    __shared__ __align__(16) unsigned As[2][128 * 20];
    __shared__ __align__(16) unsigned Bs[2][64 * 20];

    const int tid  = threadIdx.x;
    const int w    = tid >> 5;
    const int lane = tid & 31;
    const int g    = lane >> 2;
    const int c    = lane & 3;
    const int l7   = lane & 7;
    const int m0   = blockIdx.y << 7;
    const int n0   = blockIdx.x << 6;

    const unsigned* Ah = (MODE == 0) ? g_xh : (MODE == 1) ? g_yh : g_oh;
    const unsigned* Bh = (MODE == 0) ? g_wqh : (MODE == 1) ? g_wkvh : g_wph;

    unsigned aB[2], bB[2];
    #pragma unroll
    for (int p = 0; p < 2; ++p) {
        aB[p] = (unsigned)__cvta_generic_to_shared(&As[p][0]);
        bB[p] = (unsigned)__cvta_generic_to_shared(&Bs[p][0]);
    }

    // staging coords: A = 2 chunks (tid, tid+256), B = 1 chunk
    const int ar0 = tid >> 2, ac0 = tid & 3;            // chunk tid
    const int ar1 = (tid + 256) >> 2;                    // chunk tid+256
    const unsigned* asrc0 = Ah + (size_t)(m0 + ar0) * KW + ac0 * 4;
    const unsigned* asrc1 = Ah + (size_t)(m0 + ar1) * KW + ac0 * 4;
    const unsigned* bsrc  = Bh + (size_t)(n0 + ar0) * KW + ac0 * 4;

    // prologue: stage chunk 0
    cp16(aB[0] + ar0 * 80 + ac0 * 16, asrc0);
    cp16(aB[0] + ar1 * 80 + ac0 * 16, asrc1);
    cp16(bB[0] + ar0 * 80 + ac0 * 16, bsrc);
    cp_commit();

    float acc[8][4] = {};
    constexpr int NIT = K / 32;

    for (int it = 0; it < NIT; ++it) {
        const int p = it & 1;
        cp_wait0();
        __syncthreads();

        if (it + 1 < NIT) {
            const int kw = (it + 1) * 16;
            cp16(aB[p ^ 1] + ar0 * 80 + ac0 * 16, asrc0 + kw);
            cp16(aB[p ^ 1] + ar1 * 80 + ac0 * 16, asrc1 + kw);
            cp16(bB[p ^ 1] + ar0 * 80 + ac0 * 16, bsrc  + kw);
        }
        cp_commit();

        unsigned a[2][4];
        #pragma unroll
        for (int kk = 0; kk < 2; ++kk) {
            unsigned ad = aB[p] + (unsigned)((w * 16 + ((lane >> 3) & 1) * 8 + l7) * 80
                                             + ((lane >> 4) + kk * 2) * 16);
            ldsm4(a[kk][0], a[kk][1], a[kk][2], a[kk][3], ad);
        }
        #pragma unroll
        for (int j = 0; j < 8; ++j) {
            unsigned bb[4];
            unsigned bd = bB[p] + (unsigned)((j * 8 + l7) * 80 + (lane >> 3) * 16);
            ldsm4(bb[0], bb[1], bb[2], bb[3], bd);
            mma_f16(acc[j], a[0][0], a[0][1], a[0][2], a[0][3], bb[0], bb[1]);
            mma_f16(acc[j], a[1][0], a[1][1], a[1][2], a[1][3], bb[2], bb[3]);
        }
    }

    #pragma unroll
    for (int j = 0; j < 8; ++j) {
        const int n = n0 + j * 8 + 2 * c;
        #pragma unroll
        for (int half = 0; half < 2; ++half) {
            const int m = m0 + w * 16 + g + half * 8;
            float2 val = {acc[j][2 * half], acc[j][2 * half + 1]};
            if (MODE == 0) {
                const int b = m >> 12, nn = m & 4095, h = n >> 6, d = n & 63;
                g_qh[(((size_t)(b * NH + h)) * Nq + nn) * 32 + (d >> 1)] =
                    packh(val.y, val.x);
            } else if (MODE == 1) {
                const int b = m >> 12, nn = m & 4095;
                if (n < DEC) {
                    const int h = n >> 6, d = n & 63;
                    g_kh[(((size_t)(b * NH + h)) * Nkv + nn) * 32 + (d >> 1)] =
                        packh(val.y, val.x);
                } else {
                    const int n2 = n - DEC, h = n2 >> 6, d = n2 & 63;
                    g_vh[(((size_t)(b * NH + h)) * Nkv + nn) * 32 + (d >> 1)] =
                        packh(val.y, val.x);
                }
            } else {
                float2 bb = *(const float2*)&bias[n];
                val.x += bb.x; val.y += bb.y;
                *(float2*)&Cout[(size_t)m * DEC + n] = val;
            }
        }
    }
}

// ---------------------------------------------------------------------------
// Flash attention, f16 mma.m16n8k16, cp.async double-buffered KV (R12 core).
// Epilogue now writes O as packed f16x2 to g_oh (same packh rounding the
// out-proj staging used to apply).
// ---------------------------------------------------------------------------
__global__ __launch_bounds__(256, 2) void attn_kernel(const int* __restrict__ kpm)
{
    __shared__ __align__(16) unsigned KV[2][2][64 * 36];   // [stage][K/V]
    __shared__ __align__(16) int MskI[2][64];

    const int tid  = threadIdx.x;
    const int w    = tid >> 5;
    const int lane = tid & 31;
    const int g    = lane >> 2;
    const int c    = lane & 3;
    const int l7   = lane & 7;
    const int bh   = blockIdx.y;
    const int b    = bh >> 3;
    const int h    = bh & 7;
    const int n0   = blockIdx.x << 7;

    const unsigned* qb = g_qh + ((size_t)bh * Nq + n0) * 32;
    const unsigned* kb = g_kh + (size_t)bh * Nkv * 32;
    const unsigned* vb = g_vh + (size_t)bh * Nkv * 32;
    const int*      mb = kpm + b * Nkv;

    unsigned kB[2], vB[2], mB[2];
    #pragma unroll
    for (int p = 0; p < 2; ++p) {
        kB[p] = (unsigned)__cvta_generic_to_shared(&KV[p][0][0]);
        vB[p] = (unsigned)__cvta_generic_to_shared(&KV[p][1][0]);
        mB[p] = (unsigned)__cvta_generic_to_shared(&MskI[p][0]);
    }
    const unsigned HONE = 0x3C003C00u;   // f16x2 {1.0, 1.0}

    const int srow0 = tid >> 3, scol = (tid & 7) * 4;
    const int srow1 = (tid + 256) >> 3;

    // prologue: stage tile 0
    cp16(kB[0] + srow0 * 144 + scol * 4, kb + (size_t)srow0 * 32 + scol);
    cp16(kB[0] + srow1 * 144 + scol * 4, kb + (size_t)srow1 * 32 + scol);
    cp16(vB[0] + srow0 * 144 + scol * 4, vb + (size_t)srow0 * 32 + scol);
    cp16(vB[0] + srow1 * 144 + scol * 4, vb + (size_t)srow1 * 32 + scol);
    if (tid < 16) cp16(mB[0] + tid * 16, mb + tid * 4);
    cp_commit();

    // Q A-frags straight from global (one-time)
    unsigned qa[4][4];
    {
        const unsigned* q0 = qb + (size_t)(w * 16 + g) * 32;
        const unsigned* q1 = q0 + 8 * 32;
        #pragma unroll
        for (int kk = 0; kk < 4; ++kk) {
            qa[kk][0] = q0[kk * 8 + c];
            qa[kk][1] = q1[kk * 8 + c];
            qa[kk][2] = q0[kk * 8 + c + 4];
            qa[kk][3] = q1[kk * 8 + c + 4];
        }
    }

    float o[8][4] = {};
    float lacc[4] = {};
    float mr0 = -1e30f, mr1 = -1e30f;

    const unsigned krow8 = ((lane >> 3) & 1) * 8 + l7;
    const unsigned jhalf = (lane >> 4);

    for (int it = 0; it < Nkv / 64; ++it) {
        const int p = it & 1;
        cp_wait0();
        __syncthreads();

        if (it + 1 < Nkv / 64) {
            const int t1 = (it + 1) * 64;
            const unsigned* kt = kb + (size_t)t1 * 32;
            const unsigned* vt = vb + (size_t)t1 * 32;
            cp16(kB[p ^ 1] + srow0 * 144 + scol * 4, kt + (size_t)srow0 * 32 + scol);
            cp16(kB[p ^ 1] + srow1 * 144 + scol * 4, kt + (size_t)srow1 * 32 + scol);
            cp16(vB[p ^ 1] + srow0 * 144 + scol * 4, vt + (size_t)srow0 * 32 + scol);
            cp16(vB[p ^ 1] + srow1 * 144 + scol * 4, vt + (size_t)srow1 * 32 + scol);
            if (tid < 16) cp16(mB[p ^ 1] + tid * 16, mb + t1 + tid * 4);
        }
        cp_commit();

        // S = Q @ K^T
        float s[8][4] = {};
        #pragma unroll
        for (int j = 0; j < 8; ++j) {
            unsigned kf[8];
            const unsigned rowad = kB[p] + (unsigned)((j * 8 + l7) * 144 + (lane >> 3) * 16);
            ldsm4(kf[0], kf[1], kf[2], kf[3], rowad);
            ldsm4(kf[4], kf[5], kf[6], kf[7], rowad + 64);
            #pragma unroll
            for (int kk = 0; kk < 4; ++kk)
                mma_f16(s[j], qa[kk][0], qa[kk][1], qa[kk][2], qa[kk][3],
                        kf[2 * kk], kf[2 * kk + 1]);
        }

        // scale(log2) + mask + online softmax
        const int* mi = MskI[p];
        float vm0 = -1e30f, vm1 = -1e30f;
        #pragma unroll
        for (int j = 0; j < 8; ++j) {
            const float mk0 = mi[j * 8 + 2 * c]     ? -1e30f : 0.f;
            const float mk1 = mi[j * 8 + 2 * c + 1] ? -1e30f : 0.f;
            s[j][0] = fmaf(s[j][0], SCALE_L2E, mk0);
            s[j][1] = fmaf(s[j][1], SCALE_L2E, mk1);
            s[j][2] = fmaf(s[j][2], SCALE_L2E, mk0);
            s[j][3] = fmaf(s[j][3], SCALE_L2E, mk1);
            vm0 = fmaxf(vm0, fmaxf(s[j][0], s[j][1]));
            vm1 = fmaxf(vm1, fmaxf(s[j][2], s[j][3]));
        }
        vm0 = fmaxf(vm0, __shfl_xor_sync(0xffffffffu, vm0, 1));
        vm0 = fmaxf(vm0, __shfl_xor_sync(0xffffffffu, vm0, 2));
        vm1 = fmaxf(vm1, __shfl_xor_sync(0xffffffffu, vm1, 1));
        vm1 = fmaxf(vm1, __shfl_xor_sync(0xffffffffu, vm1, 2));

        const float mn0 = fmaxf(mr0, vm0);
        const float mn1 = fmaxf(mr1, vm1);
        const float cr0 = ex2(mr0 - mn0);
        const float cr1 = ex2(mr1 - mn1);
        mr0 = mn0; mr1 = mn1;

        unsigned ph0[8], ph1[8];
        #pragma unroll
        for (int j = 0; j < 8; ++j) {
            ph0[j] = hex2(packh(s[j][1] - mn0, s[j][0] - mn0));
            ph1[j] = hex2(packh(s[j][3] - mn1, s[j][2] - mn1));
        }

        #pragma unroll
        for (int j = 0; j < 8; ++j) {
            o[j][0] *= cr0; o[j][1] *= cr0;
            o[j][2] *= cr1; o[j][3] *= cr1;
        }
        lacc[0] *= cr0; lacc[1] *= cr0;
        lacc[2] *= cr1; lacc[3] *= cr1;

        // O += P @ V ; l += P @ 1
        #pragma unroll
        for (int kk = 0; kk < 4; ++kk) {
            const unsigned pa0 = ph0[2 * kk];
            const unsigned pa1 = ph1[2 * kk];
            const unsigned pa2 = ph0[2 * kk + 1];
            const unsigned pa3 = ph1[2 * kk + 1];
            #pragma unroll
            for (int jp = 0; jp < 8; jp += 2) {
                unsigned b0, b1, b2, b3;
                const unsigned vad = vB[p] +
                    (unsigned)((16 * kk + krow8) * 144 + (jp + jhalf) * 16);
                ldsm4t(b0, b1, b2, b3, vad);
                mma_f16(o[jp],     pa0, pa1, pa2, pa3, b0, b1);
                mma_f16(o[jp + 1], pa0, pa1, pa2, pa3, b2, b3);
            }
            mma_f16(lacc, pa0, pa1, pa2, pa3, HONE, HONE);
        }
    }

    // normalize + write packed f16 to g_oh [B,N,256 words]
    const float inv0 = 1.f / lacc[0];
    const float inv1 = 1.f / lacc[2];
    unsigned* ob = g_oh + ((size_t)(b * Nq) + n0 + w * 16) * 256 + h * 32;
    #pragma unroll
    for (int j = 0; j < 8; ++j) {
        ob[(size_t)g * 256 + j * 4 + c] =
            packh(o[j][1] * inv0, o[j][0] * inv0);
        ob[(size_t)(g + 8) * 256 + j * 4 + c] =
            packh(o[j][3] * inv1, o[j][2] * inv1);
    }
}

// ---------------------------------------------------------------------------
extern "C" void kernel_launch(void* const* d_in, const int* in_sizes, int n_in,
                              void* d_out, int out_size)
{
    (void)in_sizes; (void)n_in; (void)out_size;
    const float* x   = (const float*)d_in[0];
    const float* y   = (const float*)d_in[1];
    const int*   kpm = (const int*)d_in[2];     // bool mask promoted to int32
    const float* Wq  = (const float*)d_in[3];
    const float* Wkv = (const float*)d_in[4];
    const float* Wp  = (const float*)d_in[5];
    const float* bp  = (const float*)d_in[6];
    float* out = (float*)d_out;

    // f32 -> f16 converts (memory-bound, ~13 us total)
    {
        const int nx = Bsz * Nq * DEC / 4, ny = Bsz * Nkv * ENC / 4;
        const int nwq = DEC * DEC / 4, nwkv = 2 * DEC * ENC / 4, nwp = DEC * DEC / 4;
        cvt_f16<0><<<(nx   + 255) / 256, 256>>>((const float4*)x,   nx);
        cvt_f16<1><<<(ny   + 255) / 256, 256>>>((const float4*)y,   ny);
        cvt_f16<2><<<(nwq  + 255) / 256, 256>>>((const float4*)Wq,  nwq);
        cvt_f16<3><<<(nwkv + 255) / 256, 256>>>((const float4*)Wkv, nwkv);
        cvt_f16<4><<<(nwp  + 255) / 256, 256>>>((const float4*)Wp,  nwp);
    }

    gemm_mma<0, DEC><<<dim3(DEC / 64, Bsz * Nq / 128), 256>>>(nullptr, nullptr);
    gemm_mma<1, ENC><<<dim3(2 * DEC / 64, Bsz * Nkv / 128), 256>>>(nullptr, nullptr);
    attn_kernel<<<dim3(Nq / 128, Bsz * NH), 256>>>(kpm);
    gemm_mma<2, DEC><<<dim3(DEC / 64, Bsz * Nq / 128), 256>>>(out, bp);
}

// round 14
// speedup vs baseline: 1.5521x; 1.0117x over previous
#include <cuda_runtime.h>

#define DI __device__ __forceinline__

namespace {
constexpr int Bsz = 2;
constexpr int Nq  = 4096;
constexpr int Nkv = 4096;
constexpr int ENC = 768;
constexpr int DEC = 512;
constexpr int NH  = 8;
constexpr int HD  = 64;
constexpr float SCALE_L2E = 0.125f * 1.4426950408889634f;  // SCALE * log2(e)
}

// Scratch (allocation-free). All f16 tensors stored as packed f16x2 words.
__device__ __align__(16) unsigned g_qh [(size_t)Bsz * NH * Nq  * 32];
__device__ __align__(16) unsigned g_kh [(size_t)Bsz * NH * Nkv * 32];
__device__ __align__(16) unsigned g_vh [(size_t)Bsz * NH * Nkv * 32];
__device__ __align__(16) unsigned g_oh [(size_t)Bsz * Nq * (DEC / 2)];
__device__ __align__(16) unsigned g_xh [(size_t)Bsz * Nq  * (DEC / 2)];
__device__ __align__(16) unsigned g_yh [(size_t)Bsz * Nkv * (ENC / 2)];
__device__ __align__(16) unsigned g_wqh [(size_t)DEC * (DEC / 2)];
__device__ __align__(16) unsigned g_wkvh[(size_t)2 * DEC * (ENC / 2)];
__device__ __align__(16) unsigned g_wph [(size_t)DEC * (DEC / 2)];

DI unsigned packh(float hi, float lo) {    // word = {lo, hi} f16x2
    unsigned r;
    asm("cvt.rn.f16x2.f32 %0, %1, %2;" : "=r"(r) : "f"(hi), "f"(lo));
    return r;
}

DI float ex2(float x) {
    float r;
    asm("ex2.approx.ftz.f32 %0, %1;" : "=f"(r) : "f"(x));
    return r;
}

DI unsigned hex2(unsigned x) {             // ex2 on f16x2 pair
    unsigned r;
    asm("ex2.approx.f16x2 %0, %1;" : "=r"(r) : "r"(x));
    return r;
}

DI void mma_f16(float c[4], unsigned a0, unsigned a1, unsigned a2, unsigned a3,
                unsigned b0, unsigned b1) {
    asm volatile(
        "mma.sync.aligned.m16n8k16.row.col.f32.f16.f16.f32 "
        "{%0,%1,%2,%3}, {%4,%5,%6,%7}, {%8,%9}, {%0,%1,%2,%3};"
        : "+f"(c[0]), "+f"(c[1]), "+f"(c[2]), "+f"(c[3])
        : "r"(a0), "r"(a1), "r"(a2), "r"(a3), "r"(b0), "r"(b1));
}

DI void ldsm4(unsigned& r0, unsigned& r1, unsigned& r2, unsigned& r3, unsigned addr) {
    asm volatile("ldmatrix.sync.aligned.m8n8.x4.shared.b16 {%0,%1,%2,%3}, [%4];"
                 : "=r"(r0), "=r"(r1), "=r"(r2), "=r"(r3) : "r"(addr));
}

DI void ldsm4t(unsigned& r0, unsigned& r1, unsigned& r2, unsigned& r3, unsigned addr) {
    asm volatile("ldmatrix.sync.aligned.m8n8.x4.trans.shared.b16 {%0,%1,%2,%3}, [%4];"
                 : "=r"(r0), "=r"(r1), "=r"(r2), "=r"(r3) : "r"(addr));
}

DI void cp16(unsigned dst, const void* src) {
    asm volatile("cp.async.cg.shared.global [%0], [%1], 16;" :: "r"(dst), "l"(src));
}
DI void cp_commit() { asm volatile("cp.async.commit_group;"); }
DI void cp_wait0()  { asm volatile("cp.async.wait_group 0;"); }

// ---------------------------------------------------------------------------
// Fused f32 -> packed f16x2 conversion (single launch, grid-strided cascade)
// ---------------------------------------------------------------------------
namespace {
constexpr int NX4   = Bsz * Nq  * DEC / 4;       // 1048576
constexpr int NY4   = Bsz * Nkv * ENC / 4;       // 1572864
constexpr int NWQ4  = DEC * DEC / 4;             // 65536
constexpr int NWKV4 = 2 * DEC * ENC / 4;         // 196608
constexpr int NWP4  = DEC * DEC / 4;             // 65536
constexpr int NCVT  = NX4 + NY4 + NWQ4 + NWKV4 + NWP4;
}

__global__ void cvt_all(const float4* __restrict__ x, const float4* __restrict__ y,
                        const float4* __restrict__ wq, const float4* __restrict__ wkv,
                        const float4* __restrict__ wp)
{
    int i = blockIdx.x * blockDim.x + threadIdx.x;
    if (i >= NCVT) return;
    const float4* src;
    uint2* dst;
    if (i < NX4)                       { src = x + i;    dst = (uint2*)g_xh + i; }
    else if ((i -= NX4) < NY4)         { src = y + i;    dst = (uint2*)g_yh + i; }
    else if ((i -= NY4) < NWQ4)        { src = wq + i;   dst = (uint2*)g_wqh + i; }
    else if ((i -= NWQ4) < NWKV4)      { src = wkv + i;  dst = (uint2*)g_wkvh + i; }
    else          { i -= NWKV4;          src = wp + i;   dst = (uint2*)g_wph + i; }
    float4 v = *src;
    *dst = uint2{packh(v.y, v.x), packh(v.w, v.z)};
}

// ---------------------------------------------------------------------------
// GEMM-NT, f16 m16n8k16, cp.async double-buffered staging.
// BM=128, BN=128, BK=32 (16 words). Row stride 20 words (80B = 5x16B,
// coprime 8 -> ldmatrix conflict-free). One sync per chunk.
// MODE 0: g_xh @ g_wqh -> g_qh ; MODE 1: g_yh @ g_wkvh -> g_kh/g_vh ;
// MODE 2: g_oh @ g_wph -> out + bias
// ---------------------------------------------------------------------------
template<int MODE, int K>
__global__ __launch_bounds__(256, 2) void gemm_mma(float* __restrict__ Cout,
                                                   const float* __restrict__ bias)
{
    constexpr int KW = K / 2;            // words per row
    __shared__ __align__(16) unsigned As[2][128 * 20];
    __shared__ __align__(16) unsigned Bs[2][128 * 20];

    const int tid  = threadIdx.x;
    const int w    = tid >> 5;
    const int lane = tid & 31;
    const int g    = lane >> 2;
    const int c    = lane & 3;
    const int l7   = lane & 7;
    const int m0   = blockIdx.y << 7;
    const int n0   = blockIdx.x << 7;    // 128-col tile

    const unsigned* Ah = (MODE == 0) ? g_xh : (MODE == 1) ? g_yh : g_oh;
    const unsigned* Bh = (MODE == 0) ? g_wqh : (MODE == 1) ? g_wkvh : g_wph;

    unsigned aB[2], bB[2];
    #pragma unroll
    for (int p = 0; p < 2; ++p) {
        aB[p] = (unsigned)__cvta_generic_to_shared(&As[p][0]);
        bB[p] = (unsigned)__cvta_generic_to_shared(&Bs[p][0]);
    }

    // staging coords: A and B each 2 chunks (tid, tid+256) of 16B
    const int ar0 = tid >> 2, ac0 = tid & 3;            // rows 0..63
    const int ar1 = (tid + 256) >> 2;                    // rows 64..127
    const unsigned* asrc0 = Ah + (size_t)(m0 + ar0) * KW + ac0 * 4;
    const unsigned* asrc1 = Ah + (size_t)(m0 + ar1) * KW + ac0 * 4;
    const unsigned* bsrc0 = Bh + (size_t)(n0 + ar0) * KW + ac0 * 4;
    const unsigned* bsrc1 = Bh + (size_t)(n0 + ar1) * KW + ac0 * 4;

    // prologue: stage chunk 0
    cp16(aB[0] + ar0 * 80 + ac0 * 16, asrc0);
    cp16(aB[0] + ar1 * 80 + ac0 * 16, asrc1);
    cp16(bB[0] + ar0 * 80 + ac0 * 16, bsrc0);
    cp16(bB[0] + ar1 * 80 + ac0 * 16, bsrc1);
    cp_commit();

    float acc[16][4] = {};
    constexpr int NIT = K / 32;

    for (int it = 0; it < NIT; ++it) {
        const int p = it & 1;
        cp_wait0();
        __syncthreads();

        if (it + 1 < NIT) {
            const int kw = (it + 1) * 16;
            cp16(aB[p ^ 1] + ar0 * 80 + ac0 * 16, asrc0 + kw);
            cp16(aB[p ^ 1] + ar1 * 80 + ac0 * 16, asrc1 + kw);
            cp16(bB[p ^ 1] + ar0 * 80 + ac0 * 16, bsrc0 + kw);
            cp16(bB[p ^ 1] + ar1 * 80 + ac0 * 16, bsrc1 + kw);
        }
        cp_commit();

        unsigned a[2][4];
        #pragma unroll
        for (int kk = 0; kk < 2; ++kk) {
            unsigned ad = aB[p] + (unsigned)((w * 16 + ((lane >> 3) & 1) * 8 + l7) * 80
                                             + ((lane >> 4) + kk * 2) * 16);
            ldsm4(a[kk][0], a[kk][1], a[kk][2], a[kk][3], ad);
        }
        #pragma unroll
        for (int j = 0; j < 16; ++j) {
            unsigned bb[4];
            unsigned bd = bB[p] + (unsigned)((j * 8 + l7) * 80 + (lane >> 3) * 16);
            ldsm4(bb[0], bb[1], bb[2], bb[3], bd);
            mma_f16(acc[j], a[0][0], a[0][1], a[0][2], a[0][3], bb[0], bb[1]);
            mma_f16(acc[j], a[1][0], a[1][1], a[1][2], a[1][3], bb[2], bb[3]);
        }
    }

    #pragma unroll
    for (int j = 0; j < 16; ++j) {
        const int n = n0 + j * 8 + 2 * c;
        #pragma unroll
        for (int half = 0; half < 2; ++half) {
            const int m = m0 + w * 16 + g + half * 8;
            float2 val = {acc[j][2 * half], acc[j][2 * half + 1]};
            if (MODE == 0) {
                const int b = m >> 12, nn = m & 4095, h = n >> 6, d = n & 63;
                g_qh[(((size_t)(b * NH + h)) * Nq + nn) * 32 + (d >> 1)] =
                    packh(val.y, val.x);
            } else if (MODE == 1) {
                const int b = m >> 12, nn = m & 4095;
                if (n < DEC) {
                    const int h = n >> 6, d = n & 63;
                    g_kh[(((size_t)(b * NH + h)) * Nkv + nn) * 32 + (d >> 1)] =
                        packh(val.y, val.x);
                } else {
                    const int n2 = n - DEC, h = n2 >> 6, d = n2 & 63;
                    g_vh[(((size_t)(b * NH + h)) * Nkv + nn) * 32 + (d >> 1)] =
                        packh(val.y, val.x);
                }
            } else {
                float2 bb = *(const float2*)&bias[n];
                val.x += bb.x; val.y += bb.y;
                *(float2*)&Cout[(size_t)m * DEC + n] = val;
            }
        }
    }
}

// ---------------------------------------------------------------------------
// Flash attention, f16 mma.m16n8k16, cp.async double-buffered KV (R12/R13
// passing core, unchanged).
// ---------------------------------------------------------------------------
__global__ __launch_bounds__(256, 2) void attn_kernel(const int* __restrict__ kpm)
{
    __shared__ __align__(16) unsigned KV[2][2][64 * 36];   // [stage][K/V]
    __shared__ __align__(16) int MskI[2][64];

    const int tid  = threadIdx.x;
    const int w    = tid >> 5;
    const int lane = tid & 31;
    const int g    = lane >> 2;
    const int c    = lane & 3;
    const int l7   = lane & 7;
    const int bh   = blockIdx.y;
    const int b    = bh >> 3;
    const int h    = bh & 7;
    const int n0   = blockIdx.x << 7;

    const unsigned* qb = g_qh + ((size_t)bh * Nq + n0) * 32;
    const unsigned* kb = g_kh + (size_t)bh * Nkv * 32;
    const unsigned* vb = g_vh + (size_t)bh * Nkv * 32;
    const int*      mb = kpm + b * Nkv;

    unsigned kB[2], vB[2], mB[2];
    #pragma unroll
    for (int p = 0; p < 2; ++p) {
        kB[p] = (unsigned)__cvta_generic_to_shared(&KV[p][0][0]);
        vB[p] = (unsigned)__cvta_generic_to_shared(&KV[p][1][0]);
        mB[p] = (unsigned)__cvta_generic_to_shared(&MskI[p][0]);
    }
    const unsigned HONE = 0x3C003C00u;   // f16x2 {1.0, 1.0}

    const int srow0 = tid >> 3, scol = (tid & 7) * 4;
    const int srow1 = (tid + 256) >> 3;

    // prologue: stage tile 0
    cp16(kB[0] + srow0 * 144 + scol * 4, kb + (size_t)srow0 * 32 + scol);
    cp16(kB[0] + srow1 * 144 + scol * 4, kb + (size_t)srow1 * 32 + scol);
    cp16(vB[0] + srow0 * 144 + scol * 4, vb + (size_t)srow0 * 32 + scol);
    cp16(vB[0] + srow1 * 144 + scol * 4, vb + (size_t)srow1 * 32 + scol);
    if (tid < 16) cp16(mB[0] + tid * 16, mb + tid * 4);
    cp_commit();

    // Q A-frags straight from global (one-time)
    unsigned qa[4][4];
    {
        const unsigned* q0 = qb + (size_t)(w * 16 + g) * 32;
        const unsigned* q1 = q0 + 8 * 32;
        #pragma unroll
        for (int kk = 0; kk < 4; ++kk) {
            qa[kk][0] = q0[kk * 8 + c];
            qa[kk][1] = q1[kk * 8 + c];
            qa[kk][2] = q0[kk * 8 + c + 4];
            qa[kk][3] = q1[kk * 8 + c + 4];
        }
    }

    float o[8][4] = {};
    float lacc[4] = {};
    float mr0 = -1e30f, mr1 = -1e30f;

    const unsigned krow8 = ((lane >> 3) & 1) * 8 + l7;
    const unsigned jhalf = (lane >> 4);

    for (int it = 0; it < Nkv / 64; ++it) {
        const int p = it & 1;
        cp_wait0();
        __syncthreads();

        if (it + 1 < Nkv / 64) {
            const int t1 = (it + 1) * 64;
            const unsigned* kt = kb + (size_t)t1 * 32;
            const unsigned* vt = vb + (size_t)t1 * 32;
            cp16(kB[p ^ 1] + srow0 * 144 + scol * 4, kt + (size_t)srow0 * 32 + scol);
            cp16(kB[p ^ 1] + srow1 * 144 + scol * 4, kt + (size_t)srow1 * 32 + scol);
            cp16(vB[p ^ 1] + srow0 * 144 + scol * 4, vt + (size_t)srow0 * 32 + scol);
            cp16(vB[p ^ 1] + srow1 * 144 + scol * 4, vt + (size_t)srow1 * 32 + scol);
            if (tid < 16) cp16(mB[p ^ 1] + tid * 16, mb + t1 + tid * 4);
        }
        cp_commit();

        // S = Q @ K^T
        float s[8][4] = {};
        #pragma unroll
        for (int j = 0; j < 8; ++j) {
            unsigned kf[8];
            const unsigned rowad = kB[p] + (unsigned)((j * 8 + l7) * 144 + (lane >> 3) * 16);
            ldsm4(kf[0], kf[1], kf[2], kf[3], rowad);
            ldsm4(kf[4], kf[5], kf[6], kf[7], rowad + 64);
            #pragma unroll
            for (int kk = 0; kk < 4; ++kk)
                mma_f16(s[j], qa[kk][0], qa[kk][1], qa[kk][2], qa[kk][3],
                        kf[2 * kk], kf[2 * kk + 1]);
        }

        // scale(log2) + mask + online softmax
        const int* mi = MskI[p];
        float vm0 = -1e30f, vm1 = -1e30f;
        #pragma unroll
        for (int j = 0; j < 8; ++j) {
            const float mk0 = mi[j * 8 + 2 * c]     ? -1e30f : 0.f;
            const float mk1 = mi[j * 8 + 2 * c + 1] ? -1e30f : 0.f;
            s[j][0] = fmaf(s[j][0], SCALE_L2E, mk0);
            s[j][1] = fmaf(s[j][1], SCALE_L2E, mk1);
            s[j][2] = fmaf(s[j][2], SCALE_L2E, mk0);
            s[j][3] = fmaf(s[j][3], SCALE_L2E, mk1);
            vm0 = fmaxf(vm0, fmaxf(s[j][0], s[j][1]));
            vm1 = fmaxf(vm1, fmaxf(s[j][2], s[j][3]));
        }
        vm0 = fmaxf(vm0, __shfl_xor_sync(0xffffffffu, vm0, 1));
        vm0 = fmaxf(vm0, __shfl_xor_sync(0xffffffffu, vm0, 2));
        vm1 = fmaxf(vm1, __shfl_xor_sync(0xffffffffu, vm1, 1));
        vm1 = fmaxf(vm1, __shfl_xor_sync(0xffffffffu, vm1, 2));

        const float mn0 = fmaxf(mr0, vm0);
        const float mn1 = fmaxf(mr1, vm1);
        const float cr0 = ex2(mr0 - mn0);
        const float cr1 = ex2(mr1 - mn1);
        mr0 = mn0; mr1 = mn1;

        unsigned ph0[8], ph1[8];
        #pragma unroll
        for (int j = 0; j < 8; ++j) {
            ph0[j] = hex2(packh(s[j][1] - mn0, s[j][0] - mn0));
            ph1[j] = hex2(packh(s[j][3] - mn1, s[j][2] - mn1));
        }

        #pragma unroll
        for (int j = 0; j < 8; ++j) {
            o[j][0] *= cr0; o[j][1] *= cr0;
            o[j][2] *= cr1; o[j][3] *= cr1;
        }
        lacc[0] *= cr0; lacc[1] *= cr0;
        lacc[2] *= cr1; lacc[3] *= cr1;

        // O += P @ V ; l += P @ 1
        #pragma unroll
        for (int kk = 0; kk < 4; ++kk) {
            const unsigned pa0 = ph0[2 * kk];
            const unsigned pa1 = ph1[2 * kk];
            const unsigned pa2 = ph0[2 * kk + 1];
            const unsigned pa3 = ph1[2 * kk + 1];
            #pragma unroll
            for (int jp = 0; jp < 8; jp += 2) {
                unsigned b0, b1, b2, b3;
                const unsigned vad = vB[p] +
                    (unsigned)((16 * kk + krow8) * 144 + (jp + jhalf) * 16);
                ldsm4t(b0, b1, b2, b3, vad);
                mma_f16(o[jp],     pa0, pa1, pa2, pa3, b0, b1);
                mma_f16(o[jp + 1], pa0, pa1, pa2, pa3, b2, b3);
            }
            mma_f16(lacc, pa0, pa1, pa2, pa3, HONE, HONE);
        }
    }

    // normalize + write packed f16 to g_oh [B,N,256 words]
    const float inv0 = 1.f / lacc[0];
    const float inv1 = 1.f / lacc[2];
    unsigned* ob = g_oh + ((size_t)(b * Nq) + n0 + w * 16) * 256 + h * 32;
    #pragma unroll
    for (int j = 0; j < 8; ++j) {
        ob[(size_t)g * 256 + j * 4 + c] =
            packh(o[j][1] * inv0, o[j][0] * inv0);
        ob[(size_t)(g + 8) * 256 + j * 4 + c] =
            packh(o[j][3] * inv1, o[j][2] * inv1);
    }
}

// ---------------------------------------------------------------------------
extern "C" void kernel_launch(void* const* d_in, const int* in_sizes, int n_in,
                              void* d_out, int out_size)
{
    (void)in_sizes; (void)n_in; (void)out_size;
    const float* x   = (const float*)d_in[0];
    const float* y   = (const float*)d_in[1];
    const int*   kpm = (const int*)d_in[2];     // bool mask promoted to int32
    const float* Wq  = (const float*)d_in[3];
    const float* Wkv = (const float*)d_in[4];
    const float* Wp  = (const float*)d_in[5];
    const float* bp  = (const float*)d_in[6];
    float* out = (float*)d_out;

    cvt_all<<<(NCVT + 255) / 256, 256>>>((const float4*)x, (const float4*)y,
                                         (const float4*)Wq, (const float4*)Wkv,
                                         (const float4*)Wp);

    gemm_mma<0, DEC><<<dim3(DEC / 128, Bsz * Nq / 128), 256>>>(nullptr, nullptr);
    gemm_mma<1, ENC><<<dim3(2 * DEC / 128, Bsz * Nkv / 128), 256>>>(nullptr, nullptr);
    attn_kernel<<<dim3(Nq / 128, Bsz * NH), 256>>>(kpm);
    gemm_mma<2, DEC><<<dim3(DEC / 128, Bsz * Nq / 128), 256>>>(out, bp);
}